// round 2
// baseline (speedup 1.0000x reference)
#include <cuda_runtime.h>
#include <cstdint>

#define BSZ 4
#define NS  16384
#define SS  8
#define CPL 64
#define RESO 128
#define HW  (RESO*RESO)          // 16384
#define IND 192
#define NPTS (BSZ*NS)            // 65536
#define PLANE_ELEMS (BSZ*HW*CPL) // 4,194,304 per plane (all batches)

// ---- device scratch (allocation-free rule: __device__ globals) ----
__device__ float g_planes[3 * PLANE_ELEMS];   // [pl][b][y][x][c]  ~50.3MB
__device__ float g_agg[NPTS * IND];           // weighted aux sums ~50.3MB
__device__ float g_Mt[IND * IND];             // (W_out@W_v)^T : Mt[k][n]
__device__ float g_cb[IND];                   // W_out @ b_v

// ======================= K0: plane transpose [B,C,H,W] -> [B,H,W,C] ==========
__global__ void transpose_k(const float* __restrict__ p0,
                            const float* __restrict__ p1,
                            const float* __restrict__ p2) {
    __shared__ float tile[32][33];
    int z  = blockIdx.z;          // pl*4 + b
    int pl = z >> 2, b = z & 3;
    const float* src = (pl == 0 ? p0 : (pl == 1 ? p1 : p2)) + (size_t)b * CPL * HW;
    float* dst = g_planes + (size_t)pl * PLANE_ELEMS + (size_t)b * HW * CPL;
    int hw0 = blockIdx.x * 32;    // 512 tiles
    int c0  = blockIdx.y * 32;    // 2 tiles
    int tx = threadIdx.x, ty = threadIdx.y;
#pragma unroll
    for (int j = 0; j < 32; j += 8)
        tile[ty + j][tx] = src[(size_t)(c0 + ty + j) * HW + hw0 + tx];
    __syncthreads();
#pragma unroll
    for (int j = 0; j < 32; j += 8)
        dst[(size_t)(hw0 + ty + j) * CPL + c0 + tx] = tile[tx][ty + j];
}

// ======================= K1: fold weights ====================================
// block n (192), thread k (192): Mt[k][n] = sum_j W_out[n][j]*W_v[j][k]
__global__ void prep_k(const float* __restrict__ W_v,
                       const float* __restrict__ b_v,
                       const float* __restrict__ W_out) {
    int n = blockIdx.x;
    int k = threadIdx.x;
    float acc = 0.f;
#pragma unroll 4
    for (int j = 0; j < IND; j++)
        acc = fmaf(W_out[n * IND + j], W_v[j * IND + k], acc);
    g_Mt[k * IND + n] = acc;
    if (k == 0) {
        float c = 0.f;
        for (int j = 0; j < IND; j++) c = fmaf(W_out[n * IND + j], b_v[j], c);
        g_cb[n] = c;
    }
}

// ======================= bilinear tap (2 channels per lane) ==================
__device__ __forceinline__ float2 samp2(const float* __restrict__ pb,
                                        float u, float v, int c) {
    float x = __saturatef(u) * 127.0f;
    float y = __saturatef(v) * 127.0f;
    float xf = floorf(x), yf = floorf(y);
    int x0 = (int)xf, y0 = (int)yf;
    int x1 = min(x0 + 1, 127), y1 = min(y0 + 1, 127);
    float wx = x - xf, wy = y - yf;
    float2 f00 = *(const float2*)(pb + (((y0 << 7) + x0) << 6) + c);
    float2 f01 = *(const float2*)(pb + (((y0 << 7) + x1) << 6) + c);
    float2 f10 = *(const float2*)(pb + (((y1 << 7) + x0) << 6) + c);
    float2 f11 = *(const float2*)(pb + (((y1 << 7) + x1) << 6) + c);
    float w00 = (1.f - wx) * (1.f - wy), w01 = wx * (1.f - wy);
    float w10 = (1.f - wx) * wy,        w11 = wx * wy;
    float2 r;
    r.x = f00.x * w00 + f01.x * w01 + f10.x * w10 + f11.x * w11;
    r.y = f00.y * w00 + f01.y * w01 + f10.y * w10 + f11.y * w11;
    return r;
}

// ======================= K2: fused sample + offsets + weighted agg ===========
// 256 threads = 8 warps; warp handles 1 point/iter, 4 iters per block.
// grid = 2048 blocks -> 2048*4*8 = 65536 points
__global__ __launch_bounds__(256) void main_k(
    const float* __restrict__ query,
    const float* __restrict__ W_off, const float* __restrict__ b_off,
    const float* __restrict__ W_wt,  const float* __restrict__ b_wt,
    const float* __restrict__ b_out, float* __restrict__ out) {

    __shared__ float Wsh[32 * 193];      // rows 0..23 = W_off, 24..31 = W_wt (pad 193)
    __shared__ float feat[8][IND];

    // stage the 32x192 offset/weight matrix once per block
    for (int i = threadIdx.x; i < 32 * IND; i += 256) {
        int row = i / IND, col = i % IND;
        float w = (row < 24) ? W_off[row * IND + col] : W_wt[(row - 24) * IND + col];
        Wsh[row * 193 + col] = w;
    }
    __syncthreads();

    const int warp = threadIdx.x >> 5;
    const int lane = threadIdx.x & 31;
    const int c = lane * 2;

    for (int it = 0; it < 4; ++it) {
        int p = blockIdx.x * 32 + it * 8 + warp;       // 0..65535
        int b = p >> 14;
        const float* pb = g_planes + (size_t)b * HW * CPL;
        const float* P0 = pb;                            // xz
        const float* P1 = pb + PLANE_ELEMS;              // xy
        const float* P2 = pb + 2 * PLANE_ELEMS;          // yz

        float qx = query[p * 3 + 0];
        float qy = query[p * 3 + 1];
        float qz = query[p * 3 + 2];

        // feature at query
        float2 f0 = samp2(P0, qx, qz, c);
        float2 f1 = samp2(P1, qx, qy, c);
        float2 f2 = samp2(P2, qy, qz, c);
        feat[warp][c]           = f0.x; feat[warp][c + 1]       = f0.y;
        feat[warp][64 + c]      = f1.x; feat[warp][64 + c + 1]  = f1.y;
        feat[warp][128 + c]     = f2.x; feat[warp][128 + c + 1] = f2.y;
        __syncwarp();

        // 32-output GEMV: lane t computes output t (24 offsets + 8 weights)
        float o = (lane < 24) ? b_off[lane] : b_wt[lane - 24];
        const float* wrow = &Wsh[lane * 193];
        const float* frow = feat[warp];
#pragma unroll 8
        for (int k = 0; k < IND; k++) o = fmaf(frow[k], wrow[k], o);

        // sum of weights (lanes 24..31)
        float wv = (lane >= 24) ? o : 0.f;
#pragma unroll
        for (int d = 16; d; d >>= 1) wv += __shfl_xor_sync(0xffffffffu, wv, d);

        float a0 = 0.f, a1 = 0.f, a2 = 0.f, a3 = 0.f, a4 = 0.f, a5 = 0.f;
#pragma unroll 2
        for (int s = 0; s < SS; s++) {
            float ox = __shfl_sync(0xffffffffu, o, 3 * s);
            float oy = __shfl_sync(0xffffffffu, o, 3 * s + 1);
            float oz = __shfl_sync(0xffffffffu, o, 3 * s + 2);
            float ws = __shfl_sync(0xffffffffu, o, 24 + s);
            float px = qx + ox, py = qy + oy, pz = qz + oz;
            float2 s0 = samp2(P0, px, pz, c);
            float2 s1 = samp2(P1, px, py, c);
            float2 s2 = samp2(P2, py, pz, c);
            a0 = fmaf(ws, s0.x, a0); a1 = fmaf(ws, s0.y, a1);
            a2 = fmaf(ws, s1.x, a2); a3 = fmaf(ws, s1.y, a3);
            a4 = fmaf(ws, s2.x, a4); a5 = fmaf(ws, s2.y, a5);
        }

        // write agg and residual (out = feature + swt*(W_out b_v) + b_out)
        float* ar = g_agg + (size_t)p * IND;
        *(float2*)(ar + c)       = make_float2(a0, a1);
        *(float2*)(ar + 64 + c)  = make_float2(a2, a3);
        *(float2*)(ar + 128 + c) = make_float2(a4, a5);

        float* orow = out + (size_t)p * IND;
        float2 cb0 = *(const float2*)(g_cb + c);
        float2 cb1 = *(const float2*)(g_cb + 64 + c);
        float2 cb2 = *(const float2*)(g_cb + 128 + c);
        float2 bo0 = *(const float2*)(b_out + c);
        float2 bo1 = *(const float2*)(b_out + 64 + c);
        float2 bo2 = *(const float2*)(b_out + 128 + c);
        *(float2*)(orow + c) = make_float2(f0.x + wv * cb0.x + bo0.x,
                                           f0.y + wv * cb0.y + bo0.y);
        *(float2*)(orow + 64 + c) = make_float2(f1.x + wv * cb1.x + bo1.x,
                                                f1.y + wv * cb1.y + bo1.y);
        *(float2*)(orow + 128 + c) = make_float2(f2.x + wv * cb2.x + bo2.x,
                                                 f2.y + wv * cb2.y + bo2.y);
    }
}

// ======================= K3: out += agg @ M^T ================================
// block: 64 rows x all 192 cols, BK=16; 256 threads, 4x12 micro-tile each
__global__ __launch_bounds__(256) void gemm_k(float* __restrict__ out) {
    __shared__ float As[16][64];
    __shared__ float Bs[16][192];
    int row0 = blockIdx.x * 64;
    int t = threadIdx.x;
    int tm = t >> 4;      // 0..15 -> rows tm*4..tm*4+3
    int tn = t & 15;      // 0..15 -> cols tn*12..tn*12+11
    float acc[4][12];
#pragma unroll
    for (int i = 0; i < 4; i++)
#pragma unroll
        for (int j = 0; j < 12; j++) acc[i][j] = 0.f;

    for (int kk = 0; kk < IND; kk += 16) {
        // As[k][m] <- agg[row0+m][kk+k]   (each thread: one float4 along k)
        {
            int m = t >> 2, k4 = (t & 3) * 4;
            float4 v = *(const float4*)(g_agg + (size_t)(row0 + m) * IND + kk + k4);
            As[k4 + 0][m] = v.x; As[k4 + 1][m] = v.y;
            As[k4 + 2][m] = v.z; As[k4 + 3][m] = v.w;
        }
        // Bs[k][n] <- Mt[kk+k][n]  (coalesced)
#pragma unroll
        for (int i = 0; i < 12; i++) {
            int idx = t + i * 256;
            int k = idx / 192, n = idx % 192;
            Bs[k][n] = g_Mt[(size_t)(kk + k) * IND + n];
        }
        __syncthreads();
#pragma unroll
        for (int k = 0; k < 16; k++) {
            float4 av = *(const float4*)&As[k][tm * 4];
            float4 b0 = *(const float4*)&Bs[k][tn * 12];
            float4 b1 = *(const float4*)&Bs[k][tn * 12 + 4];
            float4 b2 = *(const float4*)&Bs[k][tn * 12 + 8];
            float a[4] = {av.x, av.y, av.z, av.w};
            float bb[12] = {b0.x, b0.y, b0.z, b0.w, b1.x, b1.y, b1.z, b1.w,
                            b2.x, b2.y, b2.z, b2.w};
#pragma unroll
            for (int i = 0; i < 4; i++)
#pragma unroll
                for (int j = 0; j < 12; j++)
                    acc[i][j] = fmaf(a[i], bb[j], acc[i][j]);
        }
        __syncthreads();
    }
#pragma unroll
    for (int i = 0; i < 4; i++) {
        float* orow = out + (size_t)(row0 + tm * 4 + i) * IND + tn * 12;
#pragma unroll
        for (int j = 0; j < 12; j++) orow[j] += acc[i][j];
    }
}

// ======================= launch ==============================================
extern "C" void kernel_launch(void* const* d_in, const int* in_sizes, int n_in,
                              void* d_out, int out_size) {
    const float* query = (const float*)d_in[0];
    const float* f_xz  = (const float*)d_in[1];
    const float* f_xy  = (const float*)d_in[2];
    const float* f_yz  = (const float*)d_in[3];
    const float* W_v   = (const float*)d_in[4];
    const float* b_v   = (const float*)d_in[5];
    // W_out = d_in[6], b_out = d_in[7]
    const float* W_out = (const float*)d_in[6];
    const float* b_out = (const float*)d_in[7];
    const float* W_off = (const float*)d_in[8];
    const float* b_off = (const float*)d_in[9];
    const float* W_wt  = (const float*)d_in[10];
    const float* b_wt  = (const float*)d_in[11];
    float* out = (float*)d_out;

    transpose_k<<<dim3(HW / 32, CPL / 32, 12), dim3(32, 8)>>>(f_xz, f_xy, f_yz);
    prep_k<<<IND, IND>>>(W_v, b_v, W_out);
    main_k<<<2048, 256>>>(query, W_off, b_off, W_wt, b_wt, b_out, out);
    gemm_k<<<NPTS / 64, 256>>>(out);
}

// round 4
// speedup vs baseline: 1.1136x; 1.1136x over previous
#include <cuda_runtime.h>
#include <cuda_fp16.h>
#include <cstdint>

#define BSZ 4
#define NS  16384
#define SS  8
#define CPL 64
#define RESO 128
#define HW  (RESO*RESO)          // 16384
#define IND 192
#define NPTS (BSZ*NS)            // 65536
#define PLANE_ELEMS (BSZ*HW*CPL) // 4,194,304 per plane
#define PLANE_H2    (PLANE_ELEMS/2)

// ---- device scratch (allocation-free rule: __device__ globals) ----
__device__ float   g_planes[3 * PLANE_ELEMS];   // fp32 [pl][b][y][x][c] ~50MB
__device__ __half2 g_planesh[3 * PLANE_H2];     // fp16 same layout      ~25MB
__device__ float   g_agg[NPTS * IND];           // weighted aux sums     ~50MB
__device__ float   g_Mt[IND * IND];             // (W_out@W_v)^T : Mt[k][n]
__device__ float   g_cb[IND];                   // W_out @ b_v

// ======================= K0: transpose -> fp32 + fp16 copies =================
__global__ void transpose_k(const float* __restrict__ p0,
                            const float* __restrict__ p1,
                            const float* __restrict__ p2) {
    __shared__ float tile[32][33];
    int z  = blockIdx.z;          // pl*4 + b
    int pl = z >> 2, b = z & 3;
    const float* src = (pl == 0 ? p0 : (pl == 1 ? p1 : p2)) + (size_t)b * CPL * HW;
    float*   dst  = g_planes  + (size_t)pl * PLANE_ELEMS + (size_t)b * HW * CPL;
    __half2* dst2 = g_planesh + (size_t)pl * PLANE_H2    + (size_t)b * HW * 32;
    int hw0 = blockIdx.x * 32;
    int c0  = blockIdx.y * 32;
    int tx = threadIdx.x, ty = threadIdx.y;
#pragma unroll
    for (int j = 0; j < 32; j += 8)
        tile[ty + j][tx] = src[(size_t)(c0 + ty + j) * HW + hw0 + tx];
    __syncthreads();
#pragma unroll
    for (int j = 0; j < 32; j += 8)
        dst[(size_t)(hw0 + ty + j) * CPL + c0 + tx] = tile[tx][ty + j];
    if (tx < 16) {
#pragma unroll
        for (int j = 0; j < 32; j += 8) {
            int r = ty + j;
            __half2 hv = __floats2half2_rn(tile[2 * tx][r], tile[2 * tx + 1][r]);
            dst2[(size_t)(hw0 + r) * 32 + (c0 >> 1) + tx] = hv;
        }
    }
}

// ======================= K1: fold weights ====================================
__global__ void prep_k(const float* __restrict__ W_v,
                       const float* __restrict__ b_v,
                       const float* __restrict__ W_out) {
    int n = blockIdx.x;
    int k = threadIdx.x;
    float acc = 0.f;
#pragma unroll 4
    for (int j = 0; j < IND; j++)
        acc = fmaf(W_out[n * IND + j], W_v[j * IND + k], acc);
    g_Mt[k * IND + n] = acc;
    if (k == 0) {
        float c = 0.f;
        for (int j = 0; j < IND; j++) c = fmaf(W_out[n * IND + j], b_v[j], c);
        g_cb[n] = c;
    }
}

// ======================= bilinear taps =======================================
__device__ __forceinline__ float2 samp2f(const float* __restrict__ pb,
                                         float u, float v, int c) {
    float x = __saturatef(u) * 127.0f;
    float y = __saturatef(v) * 127.0f;
    float xf = floorf(x), yf = floorf(y);
    int x0 = (int)xf, y0 = (int)yf;
    int x1 = min(x0 + 1, 127), y1 = min(y0 + 1, 127);
    float wx = x - xf, wy = y - yf;
    float2 f00 = *(const float2*)(pb + (((y0 << 7) + x0) << 6) + c);
    float2 f01 = *(const float2*)(pb + (((y0 << 7) + x1) << 6) + c);
    float2 f10 = *(const float2*)(pb + (((y1 << 7) + x0) << 6) + c);
    float2 f11 = *(const float2*)(pb + (((y1 << 7) + x1) << 6) + c);
    float w00 = (1.f - wx) * (1.f - wy), w01 = wx * (1.f - wy);
    float w10 = (1.f - wx) * wy,        w11 = wx * wy;
    float2 r;
    r.x = f00.x * w00 + f01.x * w01 + f10.x * w10 + f11.x * w11;
    r.y = f00.y * w00 + f01.y * w01 + f10.y * w10 + f11.y * w11;
    return r;
}

__device__ __forceinline__ float2 samp2h(const __half2* __restrict__ pb,
                                         float u, float v, int lane) {
    float x = __saturatef(u) * 127.0f;
    float y = __saturatef(v) * 127.0f;
    float xf = floorf(x), yf = floorf(y);
    int x0 = (int)xf, y0 = (int)yf;
    int x1 = min(x0 + 1, 127), y1 = min(y0 + 1, 127);
    float wx = x - xf, wy = y - yf;
    float2 f00 = __half22float2(pb[(((y0 << 7) + x0) << 5) + lane]);
    float2 f01 = __half22float2(pb[(((y0 << 7) + x1) << 5) + lane]);
    float2 f10 = __half22float2(pb[(((y1 << 7) + x0) << 5) + lane]);
    float2 f11 = __half22float2(pb[(((y1 << 7) + x1) << 5) + lane]);
    float w00 = (1.f - wx) * (1.f - wy), w01 = wx * (1.f - wy);
    float w10 = (1.f - wx) * wy,        w11 = wx * wy;
    float2 r;
    r.x = f00.x * w00 + f01.x * w01 + f10.x * w10 + f11.x * w11;
    r.y = f00.y * w00 + f01.y * w01 + f10.y * w10 + f11.y * w11;
    return r;
}

// ======================= K2: fused sample + offsets + weighted agg ===========
__global__ __launch_bounds__(256) void main_k(
    const float* __restrict__ query,
    const float* __restrict__ W_off, const float* __restrict__ b_off,
    const float* __restrict__ W_wt,  const float* __restrict__ b_wt,
    const float* __restrict__ b_out, float* __restrict__ out) {

    __shared__ float Wsh[32 * 193];      // rows 0..23 = W_off, 24..31 = W_wt
    __shared__ float feat[8][IND];

    for (int i = threadIdx.x; i < 32 * IND; i += 256) {
        int row = i / IND, col = i % IND;
        float w = (row < 24) ? W_off[row * IND + col] : W_wt[(row - 24) * IND + col];
        Wsh[row * 193 + col] = w;
    }
    __syncthreads();

    const int warp = threadIdx.x >> 5;
    const int lane = threadIdx.x & 31;
    const int c = lane * 2;

    for (int it = 0; it < 4; ++it) {
        int p = blockIdx.x * 32 + it * 8 + warp;
        int b = p >> 14;
        // fp32 planes (query feature: position-critical + residual)
        const float* fb = g_planes + (size_t)b * HW * CPL;
        const float* F0 = fb;
        const float* F1 = fb + PLANE_ELEMS;
        const float* F2 = fb + 2 * PLANE_ELEMS;
        // fp16 planes (aux samples: linear, small-weight)
        const __half2* hb = g_planesh + (size_t)b * HW * 32;
        const __half2* P0 = hb;
        const __half2* P1 = hb + PLANE_H2;
        const __half2* P2 = hb + 2 * PLANE_H2;

        float qx = query[p * 3 + 0];
        float qy = query[p * 3 + 1];
        float qz = query[p * 3 + 2];

        float2 f0 = samp2f(F0, qx, qz, c);
        float2 f1 = samp2f(F1, qx, qy, c);
        float2 f2 = samp2f(F2, qy, qz, c);
        feat[warp][c]           = f0.x; feat[warp][c + 1]       = f0.y;
        feat[warp][64 + c]      = f1.x; feat[warp][64 + c + 1]  = f1.y;
        feat[warp][128 + c]     = f2.x; feat[warp][128 + c + 1] = f2.y;
        __syncwarp();

        // 32-output GEMV (2 accumulators)
        float bias = (lane < 24) ? b_off[lane] : b_wt[lane - 24];
        const float* wrow = &Wsh[lane * 193];
        const float* frow = feat[warp];
        float o0 = 0.f, o1 = 0.f;
#pragma unroll 8
        for (int k = 0; k < IND; k += 2) {
            o0 = fmaf(frow[k],     wrow[k],     o0);
            o1 = fmaf(frow[k + 1], wrow[k + 1], o1);
        }
        float o = bias + o0 + o1;

        float wv = (lane >= 24) ? o : 0.f;
#pragma unroll
        for (int d = 16; d; d >>= 1) wv += __shfl_xor_sync(0xffffffffu, wv, d);

        float a0 = 0.f, a1 = 0.f, a2 = 0.f, a3 = 0.f, a4 = 0.f, a5 = 0.f;
#pragma unroll 2
        for (int s = 0; s < SS; s++) {
            float ox = __shfl_sync(0xffffffffu, o, 3 * s);
            float oy = __shfl_sync(0xffffffffu, o, 3 * s + 1);
            float oz = __shfl_sync(0xffffffffu, o, 3 * s + 2);
            float ws = __shfl_sync(0xffffffffu, o, 24 + s);
            float px = qx + ox, py = qy + oy, pz = qz + oz;
            float2 s0 = samp2h(P0, px, pz, lane);
            float2 s1 = samp2h(P1, px, py, lane);
            float2 s2 = samp2h(P2, py, pz, lane);
            a0 = fmaf(ws, s0.x, a0); a1 = fmaf(ws, s0.y, a1);
            a2 = fmaf(ws, s1.x, a2); a3 = fmaf(ws, s1.y, a3);
            a4 = fmaf(ws, s2.x, a4); a5 = fmaf(ws, s2.y, a5);
        }

        // streaming stores (evict-first) — keep planes L2-resident
        float* ar = g_agg + (size_t)p * IND;
        __stwt((float2*)(ar + c),       make_float2(a0, a1));
        __stwt((float2*)(ar + 64 + c),  make_float2(a2, a3));
        __stwt((float2*)(ar + 128 + c), make_float2(a4, a5));

        float* orow = out + (size_t)p * IND;
        float2 cb0 = *(const float2*)(g_cb + c);
        float2 cb1 = *(const float2*)(g_cb + 64 + c);
        float2 cb2 = *(const float2*)(g_cb + 128 + c);
        float2 bo0 = *(const float2*)(b_out + c);
        float2 bo1 = *(const float2*)(b_out + 64 + c);
        float2 bo2 = *(const float2*)(b_out + 128 + c);
        __stwt((float2*)(orow + c),
               make_float2(f0.x + wv * cb0.x + bo0.x, f0.y + wv * cb0.y + bo0.y));
        __stwt((float2*)(orow + 64 + c),
               make_float2(f1.x + wv * cb1.x + bo1.x, f1.y + wv * cb1.y + bo1.y));
        __stwt((float2*)(orow + 128 + c),
               make_float2(f2.x + wv * cb2.x + bo2.x, f2.y + wv * cb2.y + bo2.y));
    }
}

// ======================= K3: out += agg @ M^T  (tf32 mma.sync) ===============
__device__ __forceinline__ uint32_t f2tf32(float f) {
    uint32_t r;
    asm("cvt.rna.tf32.f32 %0, %1;" : "=r"(r) : "f"(f));
    return r;
}

__global__ __launch_bounds__(256) void gemm_k2(float* __restrict__ out) {
    __shared__ float As[64][9];      // [row][k]
    __shared__ float Bs[8][200];     // [k][n]
    int row0 = blockIdx.x * 64;
    int t = threadIdx.x;
    int warp = t >> 5, lane = t & 31;
    int wm = warp & 3;               // 4 m-warps -> rows wm*16
    int wn = warp >> 2;              // 2 n-warps -> cols wn*96
    int g = lane >> 2, t4 = lane & 3;

    float acc[12][4];
#pragma unroll
    for (int i = 0; i < 12; i++)
#pragma unroll
        for (int j = 0; j < 4; j++) acc[i][j] = 0.f;

    for (int kk = 0; kk < IND; kk += 8) {
        {   // A slice: 64 rows x 8 k
            int r = t >> 2, kq = (t & 3) * 2;
            float2 v = *(const float2*)(g_agg + (size_t)(row0 + r) * IND + kk + kq);
            As[r][kq] = v.x; As[r][kq + 1] = v.y;
        }
#pragma unroll
        for (int i = 0; i < 6; i++) {   // B slice: 8 k x 192 n
            int idx = t + i * 256;
            int k = idx / IND, n = idx - k * IND;
            Bs[k][n] = g_Mt[(size_t)(kk + k) * IND + n];
        }
        __syncthreads();

        const float* ar  = &As[wm * 16 + g][0];
        const float* ar8 = &As[wm * 16 + g + 8][0];
        uint32_t a0 = f2tf32(ar[t4]);
        uint32_t a1 = f2tf32(ar8[t4]);
        uint32_t a2 = f2tf32(ar[t4 + 4]);
        uint32_t a3 = f2tf32(ar8[t4 + 4]);

#pragma unroll
        for (int nt = 0; nt < 12; nt++) {
            int col = wn * 96 + nt * 8 + g;
            uint32_t b0 = f2tf32(Bs[t4][col]);
            uint32_t b1 = f2tf32(Bs[t4 + 4][col]);
            asm volatile(
                "mma.sync.aligned.m16n8k8.row.col.f32.tf32.tf32.f32 "
                "{%0,%1,%2,%3}, {%4,%5,%6,%7}, {%8,%9}, {%0,%1,%2,%3};"
                : "+f"(acc[nt][0]), "+f"(acc[nt][1]),
                  "+f"(acc[nt][2]), "+f"(acc[nt][3])
                : "r"(a0), "r"(a1), "r"(a2), "r"(a3), "r"(b0), "r"(b1));
        }
        __syncthreads();
    }

    int rA = row0 + wm * 16 + g;
#pragma unroll
    for (int nt = 0; nt < 12; nt++) {
        int col = wn * 96 + nt * 8 + t4 * 2;
        float2* p0 = (float2*)(out + (size_t)rA * IND + col);
        float2 v0 = *p0;
        v0.x += acc[nt][0]; v0.y += acc[nt][1];
        *p0 = v0;
        float2* p1 = (float2*)(out + (size_t)(rA + 8) * IND + col);
        float2 v1 = *p1;
        v1.x += acc[nt][2]; v1.y += acc[nt][3];
        *p1 = v1;
    }
}

// ======================= launch ==============================================
extern "C" void kernel_launch(void* const* d_in, const int* in_sizes, int n_in,
                              void* d_out, int out_size) {
    const float* query = (const float*)d_in[0];
    const float* f_xz  = (const float*)d_in[1];
    const float* f_xy  = (const float*)d_in[2];
    const float* f_yz  = (const float*)d_in[3];
    const float* W_v   = (const float*)d_in[4];
    const float* b_v   = (const float*)d_in[5];
    const float* W_out = (const float*)d_in[6];
    const float* b_out = (const float*)d_in[7];
    const float* W_off = (const float*)d_in[8];
    const float* b_off = (const float*)d_in[9];
    const float* W_wt  = (const float*)d_in[10];
    const float* b_wt  = (const float*)d_in[11];
    float* out = (float*)d_out;

    transpose_k<<<dim3(HW / 32, CPL / 32, 12), dim3(32, 8)>>>(f_xz, f_xy, f_yz);
    prep_k<<<IND, IND>>>(W_v, b_v, W_out);
    main_k<<<2048, 256>>>(query, W_off, b_off, W_wt, b_wt, b_out, out);
    gemm_k2<<<NPTS / 64, 256>>>(out);
}

// round 6
// speedup vs baseline: 1.2709x; 1.1412x over previous
#include <cuda_runtime.h>
#include <cuda_fp16.h>
#include <cstdint>

#define BSZ 4
#define NS  16384
#define SS  8
#define CPL 64
#define RESO 128
#define HW  (RESO*RESO)          // 16384
#define IND 192
#define NPTS (BSZ*NS)            // 65536
#define PLANE_ELEMS (BSZ*HW*CPL) // 4,194,304 per plane
#define PLANE_H2    (PLANE_ELEMS/2)

// ---- device scratch ----
__device__ float   g_planes[3 * PLANE_ELEMS];   // fp32 [pl][b][y][x][c] ~50MB
__device__ __half2 g_planesh[3 * PLANE_H2];     // fp16 same layout      ~25MB
__device__ float   g_agg[NPTS * IND];           // weighted aux sums (tf32-rounded)
__device__ float   g_Mt[IND * IND];             // (W_out@W_v)^T, tf32-rounded
__device__ float   g_cb[IND];                   // W_out @ b_v (fp32)

__device__ __forceinline__ uint32_t f2tf32(float f) {
    uint32_t r;
    asm("cvt.rna.tf32.f32 %0, %1;" : "=r"(r) : "f"(f));
    return r;
}
__device__ __forceinline__ float tf32r(float f) { return __uint_as_float(f2tf32(f)); }

// ======================= K0: transpose -> fp32 + fp16 copies =================
__global__ void transpose_k(const float* __restrict__ p0,
                            const float* __restrict__ p1,
                            const float* __restrict__ p2) {
    __shared__ float tile[32][33];
    int z  = blockIdx.z;          // pl*4 + b
    int pl = z >> 2, b = z & 3;
    const float* src = (pl == 0 ? p0 : (pl == 1 ? p1 : p2)) + (size_t)b * CPL * HW;
    float*   dst  = g_planes  + (size_t)pl * PLANE_ELEMS + (size_t)b * HW * CPL;
    __half2* dst2 = g_planesh + (size_t)pl * PLANE_H2    + (size_t)b * HW * 32;
    int hw0 = blockIdx.x * 32;
    int c0  = blockIdx.y * 32;
    int tx = threadIdx.x, ty = threadIdx.y;
#pragma unroll
    for (int j = 0; j < 32; j += 8)
        tile[ty + j][tx] = src[(size_t)(c0 + ty + j) * HW + hw0 + tx];
    __syncthreads();
#pragma unroll
    for (int j = 0; j < 32; j += 8)
        dst[(size_t)(hw0 + ty + j) * CPL + c0 + tx] = tile[tx][ty + j];
    if (tx < 16) {
#pragma unroll
        for (int j = 0; j < 32; j += 8) {
            int r = ty + j;
            __half2 hv = __floats2half2_rn(tile[2 * tx][r], tile[2 * tx + 1][r]);
            dst2[(size_t)(hw0 + r) * 32 + (c0 >> 1) + tx] = hv;
        }
    }
}

// ======================= K1: fold weights (Mt stored tf32-rounded) ===========
__global__ void prep_k(const float* __restrict__ W_v,
                       const float* __restrict__ b_v,
                       const float* __restrict__ W_out) {
    int n = blockIdx.x;
    int k = threadIdx.x;
    float acc = 0.f;
#pragma unroll 4
    for (int j = 0; j < IND; j++)
        acc = fmaf(W_out[n * IND + j], W_v[j * IND + k], acc);
    g_Mt[k * IND + n] = tf32r(acc);
    if (k == 0) {
        float c = 0.f;
        for (int j = 0; j < IND; j++) c = fmaf(W_out[n * IND + j], b_v[j], c);
        g_cb[n] = c;
    }
}

// ======================= bilinear taps =======================================
__device__ __forceinline__ float2 samp2f(const float* __restrict__ pb,
                                         float u, float v, int c) {
    float x = __saturatef(u) * 127.0f;
    float y = __saturatef(v) * 127.0f;
    float xf = floorf(x), yf = floorf(y);
    int x0 = (int)xf, y0 = (int)yf;
    int x1 = min(x0 + 1, 127), y1 = min(y0 + 1, 127);
    float wx = x - xf, wy = y - yf;
    float2 f00 = *(const float2*)(pb + (((y0 << 7) + x0) << 6) + c);
    float2 f01 = *(const float2*)(pb + (((y0 << 7) + x1) << 6) + c);
    float2 f10 = *(const float2*)(pb + (((y1 << 7) + x0) << 6) + c);
    float2 f11 = *(const float2*)(pb + (((y1 << 7) + x1) << 6) + c);
    float w00 = (1.f - wx) * (1.f - wy), w01 = wx * (1.f - wy);
    float w10 = (1.f - wx) * wy,        w11 = wx * wy;
    float2 r;
    r.x = f00.x * w00 + f01.x * w01 + f10.x * w10 + f11.x * w11;
    r.y = f00.y * w00 + f01.y * w01 + f10.y * w10 + f11.y * w11;
    return r;
}

__device__ __forceinline__ float2 samp2h(const __half2* __restrict__ pb,
                                         float u, float v, int lane) {
    float x = __saturatef(u) * 127.0f;
    float y = __saturatef(v) * 127.0f;
    float xf = floorf(x), yf = floorf(y);
    int x0 = (int)xf, y0 = (int)yf;
    int x1 = min(x0 + 1, 127), y1 = min(y0 + 1, 127);
    float wx = x - xf, wy = y - yf;
    float2 f00 = __half22float2(pb[(((y0 << 7) + x0) << 5) + lane]);
    float2 f01 = __half22float2(pb[(((y0 << 7) + x1) << 5) + lane]);
    float2 f10 = __half22float2(pb[(((y1 << 7) + x0) << 5) + lane]);
    float2 f11 = __half22float2(pb[(((y1 << 7) + x1) << 5) + lane]);
    float w00 = (1.f - wx) * (1.f - wy), w01 = wx * (1.f - wy);
    float w10 = (1.f - wx) * wy,        w11 = wx * wy;
    float2 r;
    r.x = f00.x * w00 + f01.x * w01 + f10.x * w10 + f11.x * w11;
    r.y = f00.y * w00 + f01.y * w01 + f10.y * w10 + f11.y * w11;
    return r;
}

// ======================= K2: fused sample + offsets + weighted agg ===========
__global__ __launch_bounds__(256, 2) void main_k(
    const float* __restrict__ query,
    const float* __restrict__ W_off, const float* __restrict__ b_off,
    const float* __restrict__ W_wt,  const float* __restrict__ b_wt,
    const float* __restrict__ b_out, float* __restrict__ out) {

    __shared__ float Wsh[32 * 193];      // rows 0..23 = W_off, 24..31 = W_wt
    __shared__ float feat[8][IND];

    for (int i = threadIdx.x; i < 32 * IND; i += 256) {
        int row = i / IND, col = i % IND;
        float w = (row < 24) ? W_off[row * IND + col] : W_wt[(row - 24) * IND + col];
        Wsh[row * 193 + col] = w;
    }
    __syncthreads();

    const int warp = threadIdx.x >> 5;
    const int lane = threadIdx.x & 31;
    const int c = lane * 2;

    // loop-invariant per-lane constants
    const float bias = (lane < 24) ? b_off[lane] : b_wt[lane - 24];
    const float2 cb0 = *(const float2*)(g_cb + c);
    const float2 cb1 = *(const float2*)(g_cb + 64 + c);
    const float2 cb2 = *(const float2*)(g_cb + 128 + c);
    const float2 bo0 = *(const float2*)(b_out + c);
    const float2 bo1 = *(const float2*)(b_out + 64 + c);
    const float2 bo2 = *(const float2*)(b_out + 128 + c);

    for (int it = 0; it < 4; ++it) {
        int p = blockIdx.x * 32 + it * 8 + warp;
        int b = p >> 14;
        const float* fb = g_planes + (size_t)b * HW * CPL;
        const float* F0 = fb;
        const float* F1 = fb + PLANE_ELEMS;
        const float* F2 = fb + 2 * PLANE_ELEMS;
        const __half2* hb = g_planesh + (size_t)b * HW * 32;
        const __half2* P0 = hb;
        const __half2* P1 = hb + PLANE_H2;
        const __half2* P2 = hb + 2 * PLANE_H2;

        float qx = query[p * 3 + 0];
        float qy = query[p * 3 + 1];
        float qz = query[p * 3 + 2];

        // fp32 query-point feature (position-critical)
        float2 f0 = samp2f(F0, qx, qz, c);
        float2 f1 = samp2f(F1, qx, qy, c);
        float2 f2 = samp2f(F2, qy, qz, c);
        feat[warp][c]           = f0.x; feat[warp][c + 1]       = f0.y;
        feat[warp][64 + c]      = f1.x; feat[warp][64 + c + 1]  = f1.y;
        feat[warp][128 + c]     = f2.x; feat[warp][128 + c + 1] = f2.y;
        __syncwarp();

        // 32-output GEMV
        const float* wrow = &Wsh[lane * 193];
        const float* frow = feat[warp];
        float o0 = 0.f, o1 = 0.f;
#pragma unroll 8
        for (int k = 0; k < IND; k += 2) {
            o0 = fmaf(frow[k],     wrow[k],     o0);
            o1 = fmaf(frow[k + 1], wrow[k + 1], o1);
        }
        float o = bias + o0 + o1;

        float wv = (lane >= 24) ? o : 0.f;
#pragma unroll
        for (int d = 16; d; d >>= 1) wv += __shfl_xor_sync(0xffffffffu, wv, d);

        // hoist ALL shuffles: positions + weights in registers, loop is pure loads
        float px[SS], py[SS], pz[SS], ws[SS];
#pragma unroll
        for (int s = 0; s < SS; s++) {
            px[s] = qx + __shfl_sync(0xffffffffu, o, 3 * s);
            py[s] = qy + __shfl_sync(0xffffffffu, o, 3 * s + 1);
            pz[s] = qz + __shfl_sync(0xffffffffu, o, 3 * s + 2);
            ws[s] = __shfl_sync(0xffffffffu, o, 24 + s);
        }

        float a0 = 0.f, a1 = 0.f, a2 = 0.f, a3 = 0.f, a4 = 0.f, a5 = 0.f;
#pragma unroll
        for (int s = 0; s < SS; s++) {
            float2 s0 = samp2h(P0, px[s], pz[s], lane);
            float2 s1 = samp2h(P1, px[s], py[s], lane);
            float2 s2 = samp2h(P2, py[s], pz[s], lane);
            a0 = fmaf(ws[s], s0.x, a0); a1 = fmaf(ws[s], s0.y, a1);
            a2 = fmaf(ws[s], s1.x, a2); a3 = fmaf(ws[s], s1.y, a3);
            a4 = fmaf(ws[s], s2.x, a4); a5 = fmaf(ws[s], s2.y, a5);
        }

        // agg stored tf32-rounded (gemm consumes as-is), streaming stores
        float* ar = g_agg + (size_t)p * IND;
        __stwt((float2*)(ar + c),       make_float2(tf32r(a0), tf32r(a1)));
        __stwt((float2*)(ar + 64 + c),  make_float2(tf32r(a2), tf32r(a3)));
        __stwt((float2*)(ar + 128 + c), make_float2(tf32r(a4), tf32r(a5)));

        float* orow = out + (size_t)p * IND;
        __stwt((float2*)(orow + c),
               make_float2(f0.x + wv * cb0.x + bo0.x, f0.y + wv * cb0.y + bo0.y));
        __stwt((float2*)(orow + 64 + c),
               make_float2(f1.x + wv * cb1.x + bo1.x, f1.y + wv * cb1.y + bo1.y));
        __stwt((float2*)(orow + 128 + c),
               make_float2(f2.x + wv * cb2.x + bo2.x, f2.y + wv * cb2.y + bo2.y));
    }
}

// ======================= K3: out += agg @ M^T  (tf32 mma, cp.async DB) =======
__device__ __forceinline__ void cp16(uint32_t smem, const void* gmem) {
    asm volatile("cp.async.ca.shared.global [%0], [%1], 16;"
                 :: "r"(smem), "l"(gmem));
}

__global__ __launch_bounds__(256) void gemm_k2(float* __restrict__ out) {
    __shared__ float As[2][64][20];    // row stride 80B (16B aligned), pad kills conflicts
    __shared__ float Bs[2][16][200];   // row stride 800B (16B aligned)
    int row0 = blockIdx.x * 64;
    int t = threadIdx.x;
    int warp = t >> 5, lane = t & 31;
    int wm = warp & 3;                 // rows wm*16
    int wn = warp >> 2;                // cols wn*96
    int g = lane >> 2, t4 = lane & 3;

    // per-thread load coords
    int arow = t >> 2, akc = (t & 3) * 4;                // A: 1 x 16B

    float acc[12][4];
#pragma unroll
    for (int i = 0; i < 12; i++)
#pragma unroll
        for (int j = 0; j < 4; j++) acc[i][j] = 0.f;

    // prologue: stage k-slice 0 into buf 0
    {
        cp16((uint32_t)__cvta_generic_to_shared(&As[0][arow][akc]),
             g_agg + (size_t)(row0 + arow) * IND + akc);
#pragma unroll
        for (int i = 0; i < 3; i++) {
            int idx = t + i * 256;
            int k = idx / 48, nc = (idx % 48) * 4;
            cp16((uint32_t)__cvta_generic_to_shared(&Bs[0][k][nc]),
                 g_Mt + (size_t)k * IND + nc);
        }
        asm volatile("cp.async.commit_group;");
    }

    int buf = 0;
    for (int i = 0; i < 12; i++) {
        asm volatile("cp.async.wait_group 0;");
        __syncthreads();
        if (i < 11) {
            int kk = (i + 1) * 16;
            cp16((uint32_t)__cvta_generic_to_shared(&As[buf ^ 1][arow][akc]),
                 g_agg + (size_t)(row0 + arow) * IND + kk + akc);
#pragma unroll
            for (int j = 0; j < 3; j++) {
                int idx = t + j * 256;
                int k = idx / 48, nc = (idx % 48) * 4;
                cp16((uint32_t)__cvta_generic_to_shared(&Bs[buf ^ 1][k][nc]),
                     g_Mt + (size_t)(kk + k) * IND + nc);
            }
            asm volatile("cp.async.commit_group;");
        }

#pragma unroll
        for (int k8 = 0; k8 < 2; k8++) {
            int kb = k8 * 8;
            uint32_t a0 = __float_as_uint(As[buf][wm * 16 + g][kb + t4]);
            uint32_t a1 = __float_as_uint(As[buf][wm * 16 + g + 8][kb + t4]);
            uint32_t a2 = __float_as_uint(As[buf][wm * 16 + g][kb + t4 + 4]);
            uint32_t a3 = __float_as_uint(As[buf][wm * 16 + g + 8][kb + t4 + 4]);
#pragma unroll
            for (int nt = 0; nt < 12; nt++) {
                int col = wn * 96 + nt * 8 + g;
                uint32_t b0 = __float_as_uint(Bs[buf][kb + t4][col]);
                uint32_t b1 = __float_as_uint(Bs[buf][kb + t4 + 4][col]);
                asm volatile(
                    "mma.sync.aligned.m16n8k8.row.col.f32.tf32.tf32.f32 "
                    "{%0,%1,%2,%3}, {%4,%5,%6,%7}, {%8,%9}, {%0,%1,%2,%3};"
                    : "+f"(acc[nt][0]), "+f"(acc[nt][1]),
                      "+f"(acc[nt][2]), "+f"(acc[nt][3])
                    : "r"(a0), "r"(a1), "r"(a2), "r"(a3), "r"(b0), "r"(b1));
            }
        }
        buf ^= 1;
    }

    int rA = row0 + wm * 16 + g;
#pragma unroll
    for (int nt = 0; nt < 12; nt++) {
        int col = wn * 96 + nt * 8 + t4 * 2;
        float2* p0 = (float2*)(out + (size_t)rA * IND + col);
        float2 v0 = *p0;
        v0.x += acc[nt][0]; v0.y += acc[nt][1];
        *p0 = v0;
        float2* p1 = (float2*)(out + (size_t)(rA + 8) * IND + col);
        float2 v1 = *p1;
        v1.x += acc[nt][2]; v1.y += acc[nt][3];
        *p1 = v1;
    }
}

// ======================= launch ==============================================
extern "C" void kernel_launch(void* const* d_in, const int* in_sizes, int n_in,
                              void* d_out, int out_size) {
    const float* query = (const float*)d_in[0];
    const float* f_xz  = (const float*)d_in[1];
    const float* f_xy  = (const float*)d_in[2];
    const float* f_yz  = (const float*)d_in[3];
    const float* W_v   = (const float*)d_in[4];
    const float* b_v   = (const float*)d_in[5];
    const float* W_out = (const float*)d_in[6];
    const float* b_out = (const float*)d_in[7];
    const float* W_off = (const float*)d_in[8];
    const float* b_off = (const float*)d_in[9];
    const float* W_wt  = (const float*)d_in[10];
    const float* b_wt  = (const float*)d_in[11];
    float* out = (float*)d_out;

    transpose_k<<<dim3(HW / 32, CPL / 32, 12), dim3(32, 8)>>>(f_xz, f_xy, f_yz);
    prep_k<<<IND, IND>>>(W_v, b_v, W_out);
    main_k<<<2048, 256>>>(query, W_off, b_off, W_wt, b_wt, b_out, out);
    gemm_k2<<<NPTS / 64, 256>>>(out);
}

// round 12
// speedup vs baseline: 1.3070x; 1.0285x over previous
#include <cuda_runtime.h>
#include <cuda_fp16.h>
#include <cstdint>

#define BSZ 4
#define NS  16384
#define SS  8
#define CPL 64
#define RESO 128
#define HW  (RESO*RESO)          // 16384
#define IND 192
#define NPTS (BSZ*NS)            // 65536
#define PLANE_ELEMS (BSZ*HW*CPL) // 4,194,304 per plane
#define PLANE_H2    (PLANE_ELEMS/2)

// ---- device scratch ----
__device__ float   g_planes[3 * PLANE_ELEMS];   // fp32 [pl][b][y][x][c] ~50MB (featA only)
__device__ __half2 g_planesh[3 * PLANE_H2];     // fp16 same layout ~25MB (auxB only)
__device__ float   g_rec[NPTS * 32];            // per-point: 24 pos + 8 weights (8MB)
__device__ __half2 g_aggh[NPTS * 96];           // weighted aux sums, half2 col-pairs (25MB)
__device__ __half  g_Mth[IND * IND];            // M[n][k] = (W_out@W_v)[n][k], fp16
__device__ float   g_cb[IND];                   // W_out @ b_v (fp32)

// ======================= K0: transpose -> fp32 + fp16 copies =================
__global__ void transpose_k(const float* __restrict__ p0,
                            const float* __restrict__ p1,
                            const float* __restrict__ p2) {
    __shared__ float tile[32][33];
    int z  = blockIdx.z;          // pl*4 + b
    int pl = z >> 2, b = z & 3;
    const float* src = (pl == 0 ? p0 : (pl == 1 ? p1 : p2)) + (size_t)b * CPL * HW;
    float*   dst  = g_planes  + (size_t)pl * PLANE_ELEMS + (size_t)b * HW * CPL;
    __half2* dst2 = g_planesh + (size_t)pl * PLANE_H2    + (size_t)b * HW * 32;
    int hw0 = blockIdx.x * 32;
    int c0  = blockIdx.y * 32;
    int tx = threadIdx.x, ty = threadIdx.y;
#pragma unroll
    for (int j = 0; j < 32; j += 8)
        tile[ty + j][tx] = src[(size_t)(c0 + ty + j) * HW + hw0 + tx];
    __syncthreads();
#pragma unroll
    for (int j = 0; j < 32; j += 8)
        dst[(size_t)(hw0 + ty + j) * CPL + c0 + tx] = tile[tx][ty + j];
    if (tx < 16) {
#pragma unroll
        for (int j = 0; j < 32; j += 8) {
            int r = ty + j;
            __half2 hv = __floats2half2_rn(tile[2 * tx][r], tile[2 * tx + 1][r]);
            dst2[(size_t)(hw0 + r) * 32 + (c0 >> 1) + tx] = hv;
        }
    }
}

// ======================= K1: fold weights -> fp16 M ==========================
__global__ void prep_k(const float* __restrict__ W_v,
                       const float* __restrict__ b_v,
                       const float* __restrict__ W_out) {
    int n = blockIdx.x;
    int k = threadIdx.x;
    float acc = 0.f;
#pragma unroll 4
    for (int j = 0; j < IND; j++)
        acc = fmaf(W_out[n * IND + j], W_v[j * IND + k], acc);
    g_Mth[n * IND + k] = __float2half(acc);
    if (k == 0) {
        float c = 0.f;
        for (int j = 0; j < IND; j++) c = fmaf(W_out[n * IND + j], b_v[j], c);
        g_cb[n] = c;
    }
}

// ======================= bilinear taps =======================================
__device__ __forceinline__ float2 samp2f(const float* __restrict__ pb,
                                         float u, float v, int c) {
    float x = __saturatef(u) * 127.0f;
    float y = __saturatef(v) * 127.0f;
    float xf = floorf(x), yf = floorf(y);
    int x0 = (int)xf, y0 = (int)yf;
    int x1 = min(x0 + 1, 127), y1 = min(y0 + 1, 127);
    float wx = x - xf, wy = y - yf;
    float2 f00 = *(const float2*)(pb + (((y0 << 7) + x0) << 6) + c);
    float2 f01 = *(const float2*)(pb + (((y0 << 7) + x1) << 6) + c);
    float2 f10 = *(const float2*)(pb + (((y1 << 7) + x0) << 6) + c);
    float2 f11 = *(const float2*)(pb + (((y1 << 7) + x1) << 6) + c);
    float w00 = (1.f - wx) * (1.f - wy), w01 = wx * (1.f - wy);
    float w10 = (1.f - wx) * wy,        w11 = wx * wy;
    float2 r;
    r.x = f00.x * w00 + f01.x * w01 + f10.x * w10 + f11.x * w11;
    r.y = f00.y * w00 + f01.y * w01 + f10.y * w10 + f11.y * w11;
    return r;
}

__device__ __forceinline__ float2 samp2h(const __half2* __restrict__ pb,
                                         float u, float v, int lane) {
    float x = __saturatef(u) * 127.0f;
    float y = __saturatef(v) * 127.0f;
    float xf = floorf(x), yf = floorf(y);
    int x0 = (int)xf, y0 = (int)yf;
    int x1 = min(x0 + 1, 127), y1 = min(y0 + 1, 127);
    float wx = x - xf, wy = y - yf;
    float2 f00 = __half22float2(pb[(((y0 << 7) + x0) << 5) + lane]);
    float2 f01 = __half22float2(pb[(((y0 << 7) + x1) << 5) + lane]);
    float2 f10 = __half22float2(pb[(((y1 << 7) + x0) << 5) + lane]);
    float2 f11 = __half22float2(pb[(((y1 << 7) + x1) << 5) + lane]);
    float w00 = (1.f - wx) * (1.f - wy), w01 = wx * (1.f - wy);
    float w10 = (1.f - wx) * wy,        w11 = wx * wy;
    float2 r;
    r.x = f00.x * w00 + f01.x * w01 + f10.x * w10 + f11.x * w11;
    r.y = f00.y * w00 + f01.y * w01 + f10.y * w10 + f11.y * w11;
    return r;
}

// ======================= K2a: query feature + offsets + residual =============
__global__ __launch_bounds__(256) void featA_k(
    const float* __restrict__ query,
    const float* __restrict__ W_off, const float* __restrict__ b_off,
    const float* __restrict__ W_wt,  const float* __restrict__ b_wt,
    const float* __restrict__ b_out, float* __restrict__ out) {

    __shared__ float Wsh[32 * 193];      // rows 0..23 = W_off, 24..31 = W_wt
    __shared__ float feat[8][IND];

    for (int i = threadIdx.x; i < 32 * IND; i += 256) {
        int row = i / IND, col = i % IND;
        float w = (row < 24) ? W_off[row * IND + col] : W_wt[(row - 24) * IND + col];
        Wsh[row * 193 + col] = w;
    }
    __syncthreads();

    const int warp = threadIdx.x >> 5;
    const int lane = threadIdx.x & 31;
    const int c = lane * 2;

    const float bias = (lane < 24) ? b_off[lane] : b_wt[lane - 24];
    const float2 cb0 = *(const float2*)(g_cb + c);
    const float2 cb1 = *(const float2*)(g_cb + 64 + c);
    const float2 cb2 = *(const float2*)(g_cb + 128 + c);
    const float2 bo0 = *(const float2*)(b_out + c);
    const float2 bo1 = *(const float2*)(b_out + 64 + c);
    const float2 bo2 = *(const float2*)(b_out + 128 + c);

    for (int it = 0; it < 4; ++it) {
        int p = blockIdx.x * 32 + it * 8 + warp;
        int b = p >> 14;
        const float* fb = g_planes + (size_t)b * HW * CPL;
        const float* F0 = fb;
        const float* F1 = fb + PLANE_ELEMS;
        const float* F2 = fb + 2 * PLANE_ELEMS;

        float qx = query[p * 3 + 0];
        float qy = query[p * 3 + 1];
        float qz = query[p * 3 + 2];

        float2 f0 = samp2f(F0, qx, qz, c);
        float2 f1 = samp2f(F1, qx, qy, c);
        float2 f2 = samp2f(F2, qy, qz, c);
        feat[warp][c]           = f0.x; feat[warp][c + 1]       = f0.y;
        feat[warp][64 + c]      = f1.x; feat[warp][64 + c + 1]  = f1.y;
        feat[warp][128 + c]     = f2.x; feat[warp][128 + c + 1] = f2.y;
        __syncwarp();

        const float* wrow = &Wsh[lane * 193];
        const float* frow = feat[warp];
        float o0 = 0.f, o1 = 0.f;
#pragma unroll 8
        for (int k = 0; k < IND; k += 2) {
            o0 = fmaf(frow[k],     wrow[k],     o0);
            o1 = fmaf(frow[k + 1], wrow[k + 1], o1);
        }
        float o = bias + o0 + o1;

        float wv = (lane >= 24) ? o : 0.f;
#pragma unroll
        for (int d = 16; d; d >>= 1) wv += __shfl_xor_sync(0xffffffffu, wv, d);

        // record: lanes 0..23 -> absolute sample position component, 24..31 -> weight
        float rc;
        if (lane < 24) {
            int d3 = lane - (lane / 3) * 3;
            float q = (d3 == 0) ? qx : ((d3 == 1) ? qy : qz);
            rc = o + q;
        } else {
            rc = o;
        }
        __stwt(&g_rec[(size_t)p * 32 + lane], rc);

        float* orow = out + (size_t)p * IND;
        __stwt((float2*)(orow + c),
               make_float2(f0.x + wv * cb0.x + bo0.x, f0.y + wv * cb0.y + bo0.y));
        __stwt((float2*)(orow + 64 + c),
               make_float2(f1.x + wv * cb1.x + bo1.x, f1.y + wv * cb1.y + bo1.y));
        __stwt((float2*)(orow + 128 + c),
               make_float2(f2.x + wv * cb2.x + bo2.x, f2.y + wv * cb2.y + bo2.y));
    }
}

// ======================= K2b: aux gather + weighted agg (fp16 only) ==========
__global__ __launch_bounds__(256) void auxB_k() {
    const int warp = threadIdx.x >> 5;
    const int lane = threadIdx.x & 31;

    for (int it = 0; it < 4; ++it) {
        int p = blockIdx.x * 32 + it * 8 + warp;
        int b = p >> 14;
        const __half2* hb = g_planesh + (size_t)b * HW * 32;
        const __half2* P0 = hb;
        const __half2* P1 = hb + PLANE_H2;
        const __half2* P2 = hb + 2 * PLANE_H2;

        float rc = g_rec[(size_t)p * 32 + lane];

        float px[SS], py[SS], pz[SS], ws[SS];
#pragma unroll
        for (int s = 0; s < SS; s++) {
            px[s] = __shfl_sync(0xffffffffu, rc, 3 * s);
            py[s] = __shfl_sync(0xffffffffu, rc, 3 * s + 1);
            pz[s] = __shfl_sync(0xffffffffu, rc, 3 * s + 2);
            ws[s] = __shfl_sync(0xffffffffu, rc, 24 + s);
        }

        float a0 = 0.f, a1 = 0.f, a2 = 0.f, a3 = 0.f, a4 = 0.f, a5 = 0.f;
#pragma unroll
        for (int s = 0; s < SS; s++) {
            float2 s0 = samp2h(P0, px[s], pz[s], lane);
            float2 s1 = samp2h(P1, px[s], py[s], lane);
            float2 s2 = samp2h(P2, py[s], pz[s], lane);
            a0 = fmaf(ws[s], s0.x, a0); a1 = fmaf(ws[s], s0.y, a1);
            a2 = fmaf(ws[s], s1.x, a2); a3 = fmaf(ws[s], s1.y, a3);
            a4 = fmaf(ws[s], s2.x, a4); a5 = fmaf(ws[s], s2.y, a5);
        }

        unsigned* ar = (unsigned*)(g_aggh + (size_t)p * 96);
        __half2 h0 = __floats2half2_rn(a0, a1);
        __half2 h1 = __floats2half2_rn(a2, a3);
        __half2 h2 = __floats2half2_rn(a4, a5);
        __stwt(ar + lane,      *(unsigned*)&h0);
        __stwt(ar + 32 + lane, *(unsigned*)&h1);
        __stwt(ar + 64 + lane, *(unsigned*)&h2);
    }
}

// ======================= K3: out += agg @ M^T  (fp16 mma, all-smem) ==========
// Dynamic smem: As = 64x100 half2 (25.6KB), Bs = 192x100 half2 (76.8KB)
#define AS_STRIDE 100
__global__ __launch_bounds__(256) void gemm_k3(float* __restrict__ out) {
    extern __shared__ __half2 sm[];
    __half2* As = sm;                    // [64][100]
    __half2* Bs = sm + 64 * AS_STRIDE;   // [192][100]

    int row0 = blockIdx.x * 64;
    int t = threadIdx.x;
    int warp = t >> 5, lane = t & 31;
    int wm = warp & 3;                   // rows wm*16
    int wn = warp >> 2;                  // cols wn*96
    int g = lane >> 2, t4 = lane & 3;

    // A tile: 64 rows x 96 half2 = 64*24 uint4 = 1536 (uint4 = 4 half2!)
    {
        const uint4* aggv = (const uint4*)(g_aggh + (size_t)row0 * 96);
#pragma unroll
        for (int i = 0; i < 6; i++) {
            int idx = t + i * 256;
            int r = idx / 24, jq = (idx % 24) * 4;
            *(uint4*)&As[r * AS_STRIDE + jq] = aggv[idx];
        }
        // full M: 192 rows x 96 half2 = 192*24 uint4 = 4608
        const uint4* mv = (const uint4*)g_Mth;
#pragma unroll
        for (int i = 0; i < 18; i++) {
            int idx = t + i * 256;
            int n = idx / 24, jq = (idx % 24) * 4;
            *(uint4*)&Bs[n * AS_STRIDE + jq] = mv[idx];
        }
    }
    __syncthreads();

    float acc[12][4];
#pragma unroll
    for (int i = 0; i < 12; i++)
#pragma unroll
        for (int j = 0; j < 4; j++) acc[i][j] = 0.f;

#pragma unroll
    for (int kt = 0; kt < 12; kt++) {       // 12 k-tiles of 16 halves (8 half2)
        int jb = kt * 8;
        const __half2* arow  = &As[(wm * 16 + g) * AS_STRIDE + jb];
        const __half2* arow8 = &As[(wm * 16 + g + 8) * AS_STRIDE + jb];
        uint32_t a0 = *(const uint32_t*)&arow[t4];
        uint32_t a1 = *(const uint32_t*)&arow8[t4];
        uint32_t a2 = *(const uint32_t*)&arow[t4 + 4];
        uint32_t a3 = *(const uint32_t*)&arow8[t4 + 4];
#pragma unroll
        for (int nt = 0; nt < 12; nt++) {
            int col = wn * 96 + nt * 8 + g;
            uint32_t b0 = *(const uint32_t*)&Bs[col * AS_STRIDE + jb + t4];
            uint32_t b1 = *(const uint32_t*)&Bs[col * AS_STRIDE + jb + t4 + 4];
            asm volatile(
                "mma.sync.aligned.m16n8k16.row.col.f32.f16.f16.f32 "
                "{%0,%1,%2,%3}, {%4,%5,%6,%7}, {%8,%9}, {%0,%1,%2,%3};"
                : "+f"(acc[nt][0]), "+f"(acc[nt][1]),
                  "+f"(acc[nt][2]), "+f"(acc[nt][3])
                : "r"(a0), "r"(a1), "r"(a2), "r"(a3), "r"(b0), "r"(b1));
        }
    }

    int rA = row0 + wm * 16 + g;
#pragma unroll
    for (int nt = 0; nt < 12; nt++) {
        int col = wn * 96 + nt * 8 + t4 * 2;
        float2* p0 = (float2*)(out + (size_t)rA * IND + col);
        float2 v0 = *p0;
        v0.x += acc[nt][0]; v0.y += acc[nt][1];
        *p0 = v0;
        float2* p1 = (float2*)(out + (size_t)(rA + 8) * IND + col);
        float2 v1 = *p1;
        v1.x += acc[nt][2]; v1.y += acc[nt][3];
        *p1 = v1;
    }
}

// ======================= launch ==============================================
extern "C" void kernel_launch(void* const* d_in, const int* in_sizes, int n_in,
                              void* d_out, int out_size) {
    const float* query = (const float*)d_in[0];
    const float* f_xz  = (const float*)d_in[1];
    const float* f_xy  = (const float*)d_in[2];
    const float* f_yz  = (const float*)d_in[3];
    const float* W_v   = (const float*)d_in[4];
    const float* b_v   = (const float*)d_in[5];
    const float* W_out = (const float*)d_in[6];
    const float* b_out = (const float*)d_in[7];
    const float* W_off = (const float*)d_in[8];
    const float* b_off = (const float*)d_in[9];
    const float* W_wt  = (const float*)d_in[10];
    const float* b_wt  = (const float*)d_in[11];
    float* out = (float*)d_out;

    const int gemm_smem = (64 + 192) * AS_STRIDE * 4;   // 102,400 bytes
    cudaFuncSetAttribute(gemm_k3, cudaFuncAttributeMaxDynamicSharedMemorySize,
                         gemm_smem);

    transpose_k<<<dim3(HW / 32, CPL / 32, 12), dim3(32, 8)>>>(f_xz, f_xy, f_yz);
    prep_k<<<IND, IND>>>(W_v, b_v, W_out);
    featA_k<<<2048, 256>>>(query, W_off, b_off, W_wt, b_wt, b_out, out);
    auxB_k<<<2048, 256>>>();
    gemm_k3<<<NPTS / 64, 256, gemm_smem>>>(out);
}

// round 13
// speedup vs baseline: 1.4297x; 1.0938x over previous
#include <cuda_runtime.h>
#include <cuda_fp16.h>
#include <cstdint>

#define BSZ 4
#define NS  16384
#define SS  8
#define CPL 64
#define RESO 128
#define HW  (RESO*RESO)          // 16384
#define IND 192
#define NPTS (BSZ*NS)            // 65536
#define PLANE_ELEMS (BSZ*HW*CPL) // 4,194,304 per plane
#define PLANE_H2    (PLANE_ELEMS/2)

// ---- device scratch ----
__device__ float   g_planes[3 * PLANE_ELEMS];   // fp32 [pl][b][y][x][c] ~50MB (featA)
__device__ __half2 g_planesh[3 * PLANE_H2];     // fp16 same layout ~25MB (aux)
__device__ float   g_rec[NPTS * 32];            // per-point: 24 pos + 8 weights (8MB)
__device__ __half  g_Mth[IND * IND];            // M[n][k] = (W_out@W_v)[n][k], fp16
__device__ float   g_cb[IND];                   // W_out @ b_v (fp32)

// ======================= K0: transpose -> fp32 + fp16 copies =================
__global__ void transpose_k(const float* __restrict__ p0,
                            const float* __restrict__ p1,
                            const float* __restrict__ p2) {
    __shared__ float tile[32][33];
    int z  = blockIdx.z;          // pl*4 + b
    int pl = z >> 2, b = z & 3;
    const float* src = (pl == 0 ? p0 : (pl == 1 ? p1 : p2)) + (size_t)b * CPL * HW;
    float*   dst  = g_planes  + (size_t)pl * PLANE_ELEMS + (size_t)b * HW * CPL;
    __half2* dst2 = g_planesh + (size_t)pl * PLANE_H2    + (size_t)b * HW * 32;
    int hw0 = blockIdx.x * 32;
    int c0  = blockIdx.y * 32;
    int tx = threadIdx.x, ty = threadIdx.y;
#pragma unroll
    for (int j = 0; j < 32; j += 8)
        tile[ty + j][tx] = src[(size_t)(c0 + ty + j) * HW + hw0 + tx];
    __syncthreads();
#pragma unroll
    for (int j = 0; j < 32; j += 8)
        dst[(size_t)(hw0 + ty + j) * CPL + c0 + tx] = tile[tx][ty + j];
    if (tx < 16) {
#pragma unroll
        for (int j = 0; j < 32; j += 8) {
            int r = ty + j;
            __half2 hv = __floats2half2_rn(tile[2 * tx][r], tile[2 * tx + 1][r]);
            dst2[(size_t)(hw0 + r) * 32 + (c0 >> 1) + tx] = hv;
        }
    }
}

// ======================= K1: fold weights -> fp16 M ==========================
__global__ void prep_k(const float* __restrict__ W_v,
                       const float* __restrict__ b_v,
                       const float* __restrict__ W_out) {
    int n = blockIdx.x;
    int k = threadIdx.x;
    float acc = 0.f;
#pragma unroll 4
    for (int j = 0; j < IND; j++)
        acc = fmaf(W_out[n * IND + j], W_v[j * IND + k], acc);
    g_Mth[n * IND + k] = __float2half(acc);
    if (k == 0) {
        float c = 0.f;
        for (int j = 0; j < IND; j++) c = fmaf(W_out[n * IND + j], b_v[j], c);
        g_cb[n] = c;
    }
}

// ======================= fp32 bilinear tap (2 ch / lane) =====================
__device__ __forceinline__ float2 samp2f(const float* __restrict__ pb,
                                         float u, float v, int c) {
    float x = __saturatef(u) * 127.0f;
    float y = __saturatef(v) * 127.0f;
    float xf = floorf(x), yf = floorf(y);
    int x0 = (int)xf, y0 = (int)yf;
    int x1 = min(x0 + 1, 127), y1 = min(y0 + 1, 127);
    float wx = x - xf, wy = y - yf;
    float2 f00 = *(const float2*)(pb + (((y0 << 7) + x0) << 6) + c);
    float2 f01 = *(const float2*)(pb + (((y0 << 7) + x1) << 6) + c);
    float2 f10 = *(const float2*)(pb + (((y1 << 7) + x0) << 6) + c);
    float2 f11 = *(const float2*)(pb + (((y1 << 7) + x1) << 6) + c);
    float w00 = (1.f - wx) * (1.f - wy), w01 = wx * (1.f - wy);
    float w10 = (1.f - wx) * wy,        w11 = wx * wy;
    float2 r;
    r.x = f00.x * w00 + f01.x * w01 + f10.x * w10 + f11.x * w11;
    r.y = f00.y * w00 + f01.y * w01 + f10.y * w10 + f11.y * w11;
    return r;
}

// ======================= K2a: query feature + offsets + residual =============
#define WS_STRIDE 196
__global__ __launch_bounds__(256) void featA_k(
    const float* __restrict__ query,
    const float* __restrict__ W_off, const float* __restrict__ b_off,
    const float* __restrict__ W_wt,  const float* __restrict__ b_wt,
    const float* __restrict__ b_out, float* __restrict__ out) {

    __shared__ float Wsh[32 * WS_STRIDE];   // rows 0..23 W_off, 24..31 W_wt
    __shared__ float feat[8][IND];

    for (int i = threadIdx.x; i < 32 * IND; i += 256) {
        int row = i / IND, col = i % IND;
        float w = (row < 24) ? W_off[row * IND + col] : W_wt[(row - 24) * IND + col];
        Wsh[row * WS_STRIDE + col] = w;
    }
    __syncthreads();

    const int warp = threadIdx.x >> 5;
    const int lane = threadIdx.x & 31;
    const int c = lane * 2;

    const float bias = (lane < 24) ? b_off[lane] : b_wt[lane - 24];
    const float2 cb0 = *(const float2*)(g_cb + c);
    const float2 cb1 = *(const float2*)(g_cb + 64 + c);
    const float2 cb2 = *(const float2*)(g_cb + 128 + c);
    const float2 bo0 = *(const float2*)(b_out + c);
    const float2 bo1 = *(const float2*)(b_out + 64 + c);
    const float2 bo2 = *(const float2*)(b_out + 128 + c);

    for (int it = 0; it < 4; ++it) {
        int p = blockIdx.x * 32 + it * 8 + warp;
        int b = p >> 14;
        const float* fb = g_planes + (size_t)b * HW * CPL;
        const float* F0 = fb;
        const float* F1 = fb + PLANE_ELEMS;
        const float* F2 = fb + 2 * PLANE_ELEMS;

        float qx = query[p * 3 + 0];
        float qy = query[p * 3 + 1];
        float qz = query[p * 3 + 2];

        float2 f0 = samp2f(F0, qx, qz, c);
        float2 f1 = samp2f(F1, qx, qy, c);
        float2 f2 = samp2f(F2, qy, qz, c);
        feat[warp][c]           = f0.x; feat[warp][c + 1]       = f0.y;
        feat[warp][64 + c]      = f1.x; feat[warp][64 + c + 1]  = f1.y;
        feat[warp][128 + c]     = f2.x; feat[warp][128 + c + 1] = f2.y;
        __syncwarp();

        // 32-output GEMV, float4 shared loads
        const float* wrow = &Wsh[lane * WS_STRIDE];
        const float* frow = feat[warp];
        float o0 = 0.f, o1 = 0.f, o2 = 0.f, o3 = 0.f;
#pragma unroll 6
        for (int k = 0; k < IND; k += 4) {
            float4 f = *(const float4*)(frow + k);
            float4 w = *(const float4*)(wrow + k);
            o0 = fmaf(f.x, w.x, o0); o1 = fmaf(f.y, w.y, o1);
            o2 = fmaf(f.z, w.z, o2); o3 = fmaf(f.w, w.w, o3);
        }
        float o = bias + (o0 + o1) + (o2 + o3);

        float wv = (lane >= 24) ? o : 0.f;
#pragma unroll
        for (int d = 16; d; d >>= 1) wv += __shfl_xor_sync(0xffffffffu, wv, d);

        // record: lanes 0..23 -> absolute sample pos component, 24..31 -> weight
        float rc;
        if (lane < 24) {
            int d3 = lane - (lane / 3) * 3;
            float q = (d3 == 0) ? qx : ((d3 == 1) ? qy : qz);
            rc = o + q;
        } else {
            rc = o;
        }
        __stwt(&g_rec[(size_t)p * 32 + lane], rc);

        float* orow = out + (size_t)p * IND;
        __stwt((float2*)(orow + c),
               make_float2(f0.x + wv * cb0.x + bo0.x, f0.y + wv * cb0.y + bo0.y));
        __stwt((float2*)(orow + 64 + c),
               make_float2(f1.x + wv * cb1.x + bo1.x, f1.y + wv * cb1.y + bo1.y));
        __stwt((float2*)(orow + 128 + c),
               make_float2(f2.x + wv * cb2.x + bo2.x, f2.y + wv * cb2.y + bo2.y));
    }
}

// ======================= K2b+K3 fused: aux gather + gemm =====================
// 4-channel fp16 tap: loads 2 consecutive half2 (uint2), fp32 bilerp+accum.
__device__ __forceinline__ void tap4(const __half2* __restrict__ pb,
                                     float u, float v, int l16, float ws,
                                     float2& acc0, float2& acc1) {
    float x = __saturatef(u) * 127.0f;
    float y = __saturatef(v) * 127.0f;
    float xf = floorf(x), yf = floorf(y);
    int x0 = (int)xf, y0 = (int)yf;
    int x1 = min(x0 + 1, 127), y1 = min(y0 + 1, 127);
    float wx = x - xf, wy = y - yf;
    const __half2* pl = pb + 2 * l16;
    uint2 f00 = *(const uint2*)(pl + (((y0 << 7) + x0) << 5));
    uint2 f01 = *(const uint2*)(pl + (((y0 << 7) + x1) << 5));
    uint2 f10 = *(const uint2*)(pl + (((y1 << 7) + x0) << 5));
    uint2 f11 = *(const uint2*)(pl + (((y1 << 7) + x1) << 5));
    float w00 = (1.f - wx) * (1.f - wy), w01 = wx * (1.f - wy);
    float w10 = (1.f - wx) * wy,        w11 = wx * wy;
    float ww00 = ws * w00, ww01 = ws * w01, ww10 = ws * w10, ww11 = ws * w11;
    float2 c00 = __half22float2(*(const __half2*)&f00.x);
    float2 c01 = __half22float2(*(const __half2*)&f01.x);
    float2 c10 = __half22float2(*(const __half2*)&f10.x);
    float2 c11 = __half22float2(*(const __half2*)&f11.x);
    acc0.x = fmaf(ww00, c00.x, fmaf(ww01, c01.x, fmaf(ww10, c10.x, fmaf(ww11, c11.x, acc0.x))));
    acc0.y = fmaf(ww00, c00.y, fmaf(ww01, c01.y, fmaf(ww10, c10.y, fmaf(ww11, c11.y, acc0.y))));
    float2 d00 = __half22float2(*(const __half2*)&f00.y);
    float2 d01 = __half22float2(*(const __half2*)&f01.y);
    float2 d10 = __half22float2(*(const __half2*)&f10.y);
    float2 d11 = __half22float2(*(const __half2*)&f11.y);
    acc1.x = fmaf(ww00, d00.x, fmaf(ww01, d01.x, fmaf(ww10, d10.x, fmaf(ww11, d11.x, acc1.x))));
    acc1.y = fmaf(ww00, d00.y, fmaf(ww01, d01.y, fmaf(ww10, d10.y, fmaf(ww11, d11.y, acc1.y))));
}

__device__ __forceinline__ void cp16(uint32_t smem, const void* gmem) {
    asm volatile("cp.async.ca.shared.global [%0], [%1], 16;"
                 :: "r"(smem), "l"(gmem));
}

#define AS_STRIDE 100
__global__ __launch_bounds__(256, 2) void auxgemm_k(float* __restrict__ out) {
    extern __shared__ __half2 sm[];
    __half2* As = sm;                    // [64][100]  agg tile (built in-place)
    __half2* Bs = sm + 64 * AS_STRIDE;   // [192][100] M matrix

    int t = threadIdx.x;
    int warp = t >> 5, lane = t & 31;
    int hw = lane >> 4, l16 = lane & 15;

    // prefetch full M (73.7KB) — overlaps the aux gather phase
    {
        const uint4* mv = (const uint4*)g_Mth;
#pragma unroll
        for (int i = 0; i < 18; i++) {
            int idx = t + i * 256;
            int n = idx / 24, jq = (idx % 24) * 4;
            cp16((uint32_t)__cvta_generic_to_shared(&Bs[n * AS_STRIDE + jq]), mv + idx);
        }
        asm volatile("cp.async.commit_group;");
    }

    // ---- aux phase: 64 points per block, 8 per warp ----
    for (int it = 0; it < 8; ++it) {
        int row = it * 8 + warp;                 // local 0..63
        int p = blockIdx.x * 64 + row;
        int b = p >> 14;
        const __half2* hb = g_planesh + (size_t)b * HW * 32;
        const __half2* P0 = hb;
        const __half2* P1 = hb + PLANE_H2;
        const __half2* P2 = hb + 2 * PLANE_H2;

        float rc = g_rec[(size_t)p * 32 + lane];

        // this lane handles samples {hw, 2+hw, 4+hw, 6+hw}
        float px[4], py[4], pz[4], ws[4];
#pragma unroll
        for (int s = 0; s < 4; s++) {
            int smp = 2 * s + hw;
            px[s] = __shfl_sync(0xffffffffu, rc, 3 * smp);
            py[s] = __shfl_sync(0xffffffffu, rc, 3 * smp + 1);
            pz[s] = __shfl_sync(0xffffffffu, rc, 3 * smp + 2);
            ws[s] = __shfl_sync(0xffffffffu, rc, 24 + smp);
        }

        float2 a00 = {0.f, 0.f}, a01 = {0.f, 0.f};
        float2 a10 = {0.f, 0.f}, a11 = {0.f, 0.f};
        float2 a20 = {0.f, 0.f}, a21 = {0.f, 0.f};
#pragma unroll
        for (int s = 0; s < 4; s++) {
            tap4(P0, px[s], pz[s], l16, ws[s], a00, a01);
            tap4(P1, px[s], py[s], l16, ws[s], a10, a11);
            tap4(P2, py[s], pz[s], l16, ws[s], a20, a21);
        }

        // combine even/odd-sample halves
#pragma unroll
        for (int k = 0; k < 1; k++) { /* keep scope */ }
        a00.x += __shfl_xor_sync(0xffffffffu, a00.x, 16);
        a00.y += __shfl_xor_sync(0xffffffffu, a00.y, 16);
        a01.x += __shfl_xor_sync(0xffffffffu, a01.x, 16);
        a01.y += __shfl_xor_sync(0xffffffffu, a01.y, 16);
        a10.x += __shfl_xor_sync(0xffffffffu, a10.x, 16);
        a10.y += __shfl_xor_sync(0xffffffffu, a10.y, 16);
        a11.x += __shfl_xor_sync(0xffffffffu, a11.x, 16);
        a11.y += __shfl_xor_sync(0xffffffffu, a11.y, 16);
        a20.x += __shfl_xor_sync(0xffffffffu, a20.x, 16);
        a20.y += __shfl_xor_sync(0xffffffffu, a20.y, 16);
        a21.x += __shfl_xor_sync(0xffffffffu, a21.x, 16);
        a21.y += __shfl_xor_sync(0xffffffffu, a21.y, 16);

        if (hw == 0) {
            // lane l16 covers channels 4*l16..4*l16+3 of each plane:
            // half2 cols pl*32 + 2*l16, pl*32 + 2*l16 + 1
            __half2* arow = &As[row * AS_STRIDE];
            uint2 v0, v1, v2;
            __half2 h;
            h = __floats2half2_rn(a00.x, a00.y); v0.x = *(uint32_t*)&h;
            h = __floats2half2_rn(a01.x, a01.y); v0.y = *(uint32_t*)&h;
            h = __floats2half2_rn(a10.x, a10.y); v1.x = *(uint32_t*)&h;
            h = __floats2half2_rn(a11.x, a11.y); v1.y = *(uint32_t*)&h;
            h = __floats2half2_rn(a20.x, a20.y); v2.x = *(uint32_t*)&h;
            h = __floats2half2_rn(a21.x, a21.y); v2.y = *(uint32_t*)&h;
            *(uint2*)(arow + 2 * l16)      = v0;
            *(uint2*)(arow + 32 + 2 * l16) = v1;
            *(uint2*)(arow + 64 + 2 * l16) = v2;
        }
    }

    asm volatile("cp.async.wait_group 0;");
    __syncthreads();

    // ---- gemm phase: out[64 x 192] += As(64x192) @ M^T ----
    int wm = warp & 3;                   // rows wm*16
    int wn = warp >> 2;                  // cols wn*96
    int g = lane >> 2, t4 = lane & 3;
    int row0 = blockIdx.x * 64;

    float acc[12][4];
#pragma unroll
    for (int i = 0; i < 12; i++)
#pragma unroll
        for (int j = 0; j < 4; j++) acc[i][j] = 0.f;

#pragma unroll
    for (int kt = 0; kt < 12; kt++) {       // 12 k-tiles of 16 halves (8 half2)
        int jb = kt * 8;
        const __half2* arow  = &As[(wm * 16 + g) * AS_STRIDE + jb];
        const __half2* arow8 = &As[(wm * 16 + g + 8) * AS_STRIDE + jb];
        uint32_t a0 = *(const uint32_t*)&arow[t4];
        uint32_t a1 = *(const uint32_t*)&arow8[t4];
        uint32_t a2 = *(const uint32_t*)&arow[t4 + 4];
        uint32_t a3 = *(const uint32_t*)&arow8[t4 + 4];
#pragma unroll
        for (int nt = 0; nt < 12; nt++) {
            int col = wn * 96 + nt * 8 + g;
            uint32_t b0 = *(const uint32_t*)&Bs[col * AS_STRIDE + jb + t4];
            uint32_t b1 = *(const uint32_t*)&Bs[col * AS_STRIDE + jb + t4 + 4];
            asm volatile(
                "mma.sync.aligned.m16n8k16.row.col.f32.f16.f16.f32 "
                "{%0,%1,%2,%3}, {%4,%5,%6,%7}, {%8,%9}, {%0,%1,%2,%3};"
                : "+f"(acc[nt][0]), "+f"(acc[nt][1]),
                  "+f"(acc[nt][2]), "+f"(acc[nt][3])
                : "r"(a0), "r"(a1), "r"(a2), "r"(a3), "r"(b0), "r"(b1));
        }
    }

    int rA = row0 + wm * 16 + g;
#pragma unroll
    for (int nt = 0; nt < 12; nt++) {
        int col = wn * 96 + nt * 8 + t4 * 2;
        float2* p0 = (float2*)(out + (size_t)rA * IND + col);
        float2 v0 = *p0;
        v0.x += acc[nt][0]; v0.y += acc[nt][1];
        *p0 = v0;
        float2* p1 = (float2*)(out + (size_t)(rA + 8) * IND + col);
        float2 v1 = *p1;
        v1.x += acc[nt][2]; v1.y += acc[nt][3];
        *p1 = v1;
    }
}

// ======================= launch ==============================================
extern "C" void kernel_launch(void* const* d_in, const int* in_sizes, int n_in,
                              void* d_out, int out_size) {
    const float* query = (const float*)d_in[0];
    const float* f_xz  = (const float*)d_in[1];
    const float* f_xy  = (const float*)d_in[2];
    const float* f_yz  = (const float*)d_in[3];
    const float* W_v   = (const float*)d_in[4];
    const float* b_v   = (const float*)d_in[5];
    const float* W_out = (const float*)d_in[6];
    const float* b_out = (const float*)d_in[7];
    const float* W_off = (const float*)d_in[8];
    const float* b_off = (const float*)d_in[9];
    const float* W_wt  = (const float*)d_in[10];
    const float* b_wt  = (const float*)d_in[11];
    float* out = (float*)d_out;

    const int gemm_smem = (64 + 192) * AS_STRIDE * 4;   // 102,400 bytes
    cudaFuncSetAttribute(auxgemm_k, cudaFuncAttributeMaxDynamicSharedMemorySize,
                         gemm_smem);

    transpose_k<<<dim3(HW / 32, CPL / 32, 12), dim3(32, 8)>>>(f_xz, f_xy, f_yz);
    prep_k<<<IND, IND>>>(W_v, b_v, W_out);
    featA_k<<<2048, 256>>>(query, W_off, b_off, W_wt, b_wt, b_out, out);
    auxgemm_k<<<NPTS / 64, 256, gemm_smem>>>(out);
}

// round 14
// speedup vs baseline: 1.5889x; 1.1114x over previous
#include <cuda_runtime.h>
#include <cuda_fp16.h>
#include <cstdint>

#define BSZ 4
#define NS  16384
#define SS  8
#define CPL 64
#define RESO 128
#define HW  (RESO*RESO)          // 16384
#define IND 192
#define NPTS (BSZ*NS)            // 65536
#define PLANE_ELEMS (BSZ*HW*CPL) // 4,194,304 per plane
#define PLANE_H2    (PLANE_ELEMS/2)

// ---- device scratch ----
__device__ float   g_planes[3 * PLANE_ELEMS];   // fp32 [pl][b][y][x][c] ~50MB (featA)
__device__ __half2 g_planesh[3 * PLANE_H2];     // fp16 same layout ~25MB (aux)
__device__ float   g_rec[NPTS * 32];            // per-point: 24 pos + 8 weights (8MB)
__device__ __half  g_Mth[IND * IND];            // M[n][k] = (W_out@W_v)[n][k], fp16
__device__ float   g_cb[IND];                   // W_out @ b_v (fp32)

// ======================= K0: transpose -> fp32 + fp16 copies =================
__global__ void transpose_k(const float* __restrict__ p0,
                            const float* __restrict__ p1,
                            const float* __restrict__ p2) {
    __shared__ float tile[32][33];
    int z  = blockIdx.z;          // pl*4 + b
    int pl = z >> 2, b = z & 3;
    const float* src = (pl == 0 ? p0 : (pl == 1 ? p1 : p2)) + (size_t)b * CPL * HW;
    float*   dst  = g_planes  + (size_t)pl * PLANE_ELEMS + (size_t)b * HW * CPL;
    __half2* dst2 = g_planesh + (size_t)pl * PLANE_H2    + (size_t)b * HW * 32;
    int hw0 = blockIdx.x * 32;
    int c0  = blockIdx.y * 32;
    int tx = threadIdx.x, ty = threadIdx.y;
#pragma unroll
    for (int j = 0; j < 32; j += 8)
        tile[ty + j][tx] = src[(size_t)(c0 + ty + j) * HW + hw0 + tx];
    __syncthreads();
#pragma unroll
    for (int j = 0; j < 32; j += 8)
        dst[(size_t)(hw0 + ty + j) * CPL + c0 + tx] = tile[tx][ty + j];
    if (tx < 16) {
#pragma unroll
        for (int j = 0; j < 32; j += 8) {
            int r = ty + j;
            __half2 hv = __floats2half2_rn(tile[2 * tx][r], tile[2 * tx + 1][r]);
            dst2[(size_t)(hw0 + r) * 32 + (c0 >> 1) + tx] = hv;
        }
    }
}

// ======================= K1: fold weights -> fp16 M ==========================
__global__ void prep_k(const float* __restrict__ W_v,
                       const float* __restrict__ b_v,
                       const float* __restrict__ W_out) {
    int n = blockIdx.x;
    int k = threadIdx.x;
    float acc = 0.f;
#pragma unroll 4
    for (int j = 0; j < IND; j++)
        acc = fmaf(W_out[n * IND + j], W_v[j * IND + k], acc);
    g_Mth[n * IND + k] = __float2half(acc);
    if (k == 0) {
        float c = 0.f;
        for (int j = 0; j < IND; j++) c = fmaf(W_out[n * IND + j], b_v[j], c);
        g_cb[n] = c;
    }
}

// ======================= fp32 bilinear tap (2 ch / lane) =====================
__device__ __forceinline__ float2 samp2f(const float* __restrict__ pb,
                                         float u, float v, int c) {
    float x = __saturatef(u) * 127.0f;
    float y = __saturatef(v) * 127.0f;
    float xf = floorf(x), yf = floorf(y);
    int x0 = (int)xf, y0 = (int)yf;
    int x1 = min(x0 + 1, 127), y1 = min(y0 + 1, 127);
    float wx = x - xf, wy = y - yf;
    float2 f00 = *(const float2*)(pb + (((y0 << 7) + x0) << 6) + c);
    float2 f01 = *(const float2*)(pb + (((y0 << 7) + x1) << 6) + c);
    float2 f10 = *(const float2*)(pb + (((y1 << 7) + x0) << 6) + c);
    float2 f11 = *(const float2*)(pb + (((y1 << 7) + x1) << 6) + c);
    float w00 = (1.f - wx) * (1.f - wy), w01 = wx * (1.f - wy);
    float w10 = (1.f - wx) * wy,        w11 = wx * wy;
    float2 r;
    r.x = f00.x * w00 + f01.x * w01 + f10.x * w10 + f11.x * w11;
    r.y = f00.y * w00 + f01.y * w01 + f10.y * w10 + f11.y * w11;
    return r;
}

// ======================= K2a: query feature + offsets + residual =============
// Warp processes 4 points: taps first, then ONE batched GEMV pass where each
// W fragment (lane-distinct LDS.128) is applied to 4 broadcast feat fragments.
#define WS_STRIDE 196
__global__ __launch_bounds__(256) void featA_k(
    const float* __restrict__ query,
    const float* __restrict__ W_off, const float* __restrict__ b_off,
    const float* __restrict__ W_wt,  const float* __restrict__ b_wt,
    const float* __restrict__ b_out, float* __restrict__ out) {

    __shared__ float Wsh[32 * WS_STRIDE];   // rows 0..23 W_off, 24..31 W_wt
    __shared__ float feat[32][IND];         // row = warp*4 + j

    for (int i = threadIdx.x; i < 32 * IND; i += 256) {
        int row = i / IND, col = i % IND;
        float w = (row < 24) ? W_off[row * IND + col] : W_wt[(row - 24) * IND + col];
        Wsh[row * WS_STRIDE + col] = w;
    }
    __syncthreads();

    const int warp = threadIdx.x >> 5;
    const int lane = threadIdx.x & 31;
    const int c = lane * 2;

    const float bias = (lane < 24) ? b_off[lane] : b_wt[lane - 24];
    const float2 cb0 = *(const float2*)(g_cb + c);
    const float2 cb1 = *(const float2*)(g_cb + 64 + c);
    const float2 cb2 = *(const float2*)(g_cb + 128 + c);
    const float2 bo0 = *(const float2*)(b_out + c);
    const float2 bo1 = *(const float2*)(b_out + 64 + c);
    const float2 bo2 = *(const float2*)(b_out + 128 + c);

    const int pbase = blockIdx.x * 32 + warp * 4;

    // ---- taps: 4 points ----
    float2 fr[4][3];
    float  qv[4][3];
#pragma unroll
    for (int j = 0; j < 4; j++) {
        int p = pbase + j;
        int b = p >> 14;
        const float* fb = g_planes + (size_t)b * HW * CPL;
        const float* F0 = fb;
        const float* F1 = fb + PLANE_ELEMS;
        const float* F2 = fb + 2 * PLANE_ELEMS;

        float qx = query[p * 3 + 0];
        float qy = query[p * 3 + 1];
        float qz = query[p * 3 + 2];
        qv[j][0] = qx; qv[j][1] = qy; qv[j][2] = qz;

        float2 f0 = samp2f(F0, qx, qz, c);
        float2 f1 = samp2f(F1, qx, qy, c);
        float2 f2 = samp2f(F2, qy, qz, c);
        fr[j][0] = f0; fr[j][1] = f1; fr[j][2] = f2;
        int row = warp * 4 + j;
        feat[row][c]           = f0.x; feat[row][c + 1]       = f0.y;
        feat[row][64 + c]      = f1.x; feat[row][64 + c + 1]  = f1.y;
        feat[row][128 + c]     = f2.x; feat[row][128 + c + 1] = f2.y;
    }
    __syncwarp();

    // ---- batched GEMV: 1 W pass for 4 points ----
    float o[4] = {bias, bias, bias, bias};
    const float* wrow = &Wsh[lane * WS_STRIDE];
    const float* f0r = feat[warp * 4 + 0];
    const float* f1r = feat[warp * 4 + 1];
    const float* f2r = feat[warp * 4 + 2];
    const float* f3r = feat[warp * 4 + 3];
#pragma unroll 6
    for (int k = 0; k < IND; k += 4) {
        float4 w = *(const float4*)(wrow + k);
        float4 a = *(const float4*)(f0r + k);
        float4 bq = *(const float4*)(f1r + k);
        float4 cq = *(const float4*)(f2r + k);
        float4 d = *(const float4*)(f3r + k);
        o[0] = fmaf(a.x,  w.x, fmaf(a.y,  w.y, fmaf(a.z,  w.z, fmaf(a.w,  w.w, o[0]))));
        o[1] = fmaf(bq.x, w.x, fmaf(bq.y, w.y, fmaf(bq.z, w.z, fmaf(bq.w, w.w, o[1]))));
        o[2] = fmaf(cq.x, w.x, fmaf(cq.y, w.y, fmaf(cq.z, w.z, fmaf(cq.w, w.w, o[2]))));
        o[3] = fmaf(d.x,  w.x, fmaf(d.y,  w.y, fmaf(d.z,  w.z, fmaf(d.w,  w.w, o[3]))));
    }

    // ---- per-point epilogue ----
#pragma unroll
    for (int j = 0; j < 4; j++) {
        int p = pbase + j;
        float oj = o[j];

        float wv = (lane >= 24) ? oj : 0.f;
#pragma unroll
        for (int d = 16; d; d >>= 1) wv += __shfl_xor_sync(0xffffffffu, wv, d);

        float rc;
        if (lane < 24) {
            int d3 = lane - (lane / 3) * 3;
            rc = oj + qv[j][d3];
        } else {
            rc = oj;
        }
        __stwt(&g_rec[(size_t)p * 32 + lane], rc);

        float2 f0 = fr[j][0], f1 = fr[j][1], f2 = fr[j][2];
        float* orow = out + (size_t)p * IND;
        __stwt((float2*)(orow + c),
               make_float2(f0.x + wv * cb0.x + bo0.x, f0.y + wv * cb0.y + bo0.y));
        __stwt((float2*)(orow + 64 + c),
               make_float2(f1.x + wv * cb1.x + bo1.x, f1.y + wv * cb1.y + bo1.y));
        __stwt((float2*)(orow + 128 + c),
               make_float2(f2.x + wv * cb2.x + bo2.x, f2.y + wv * cb2.y + bo2.y));
    }
}

// ======================= K2b+K3 fused: aux gather + gemm =====================
__device__ __forceinline__ void tap4(const __half2* __restrict__ pb,
                                     float u, float v, int l16, float ws,
                                     float2& acc0, float2& acc1) {
    float x = __saturatef(u) * 127.0f;
    float y = __saturatef(v) * 127.0f;
    float xf = floorf(x), yf = floorf(y);
    int x0 = (int)xf, y0 = (int)yf;
    int x1 = min(x0 + 1, 127), y1 = min(y0 + 1, 127);
    float wx = x - xf, wy = y - yf;
    const __half2* pl = pb + 2 * l16;
    uint2 f00 = *(const uint2*)(pl + (((y0 << 7) + x0) << 5));
    uint2 f01 = *(const uint2*)(pl + (((y0 << 7) + x1) << 5));
    uint2 f10 = *(const uint2*)(pl + (((y1 << 7) + x0) << 5));
    uint2 f11 = *(const uint2*)(pl + (((y1 << 7) + x1) << 5));
    float w00 = (1.f - wx) * (1.f - wy), w01 = wx * (1.f - wy);
    float w10 = (1.f - wx) * wy,        w11 = wx * wy;
    float ww00 = ws * w00, ww01 = ws * w01, ww10 = ws * w10, ww11 = ws * w11;
    float2 c00 = __half22float2(*(const __half2*)&f00.x);
    float2 c01 = __half22float2(*(const __half2*)&f01.x);
    float2 c10 = __half22float2(*(const __half2*)&f10.x);
    float2 c11 = __half22float2(*(const __half2*)&f11.x);
    acc0.x = fmaf(ww00, c00.x, fmaf(ww01, c01.x, fmaf(ww10, c10.x, fmaf(ww11, c11.x, acc0.x))));
    acc0.y = fmaf(ww00, c00.y, fmaf(ww01, c01.y, fmaf(ww10, c10.y, fmaf(ww11, c11.y, acc0.y))));
    float2 d00 = __half22float2(*(const __half2*)&f00.y);
    float2 d01 = __half22float2(*(const __half2*)&f01.y);
    float2 d10 = __half22float2(*(const __half2*)&f10.y);
    float2 d11 = __half22float2(*(const __half2*)&f11.y);
    acc1.x = fmaf(ww00, d00.x, fmaf(ww01, d01.x, fmaf(ww10, d10.x, fmaf(ww11, d11.x, acc1.x))));
    acc1.y = fmaf(ww00, d00.y, fmaf(ww01, d01.y, fmaf(ww10, d10.y, fmaf(ww11, d11.y, acc1.y))));
}

__device__ __forceinline__ void cp16(uint32_t smem, const void* gmem) {
    asm volatile("cp.async.ca.shared.global [%0], [%1], 16;"
                 :: "r"(smem), "l"(gmem));
}

#define AS_STRIDE 100
__global__ __launch_bounds__(256, 2) void auxgemm_k(float* __restrict__ out) {
    extern __shared__ __half2 sm[];
    __half2* As = sm;                    // [64][100]  agg tile (built in-place)
    __half2* Bs = sm + 64 * AS_STRIDE;   // [192][100] M matrix

    int t = threadIdx.x;
    int warp = t >> 5, lane = t & 31;
    int hw = lane >> 4, l16 = lane & 15;

    // prefetch full M (73.7KB) — overlaps the aux gather phase
    {
        const uint4* mv = (const uint4*)g_Mth;
#pragma unroll
        for (int i = 0; i < 18; i++) {
            int idx = t + i * 256;
            int n = idx / 24, jq = (idx % 24) * 4;
            cp16((uint32_t)__cvta_generic_to_shared(&Bs[n * AS_STRIDE + jq]), mv + idx);
        }
        asm volatile("cp.async.commit_group;");
    }

    // ---- aux phase: 64 points per block, 8 per warp ----
    for (int it = 0; it < 8; ++it) {
        int row = it * 8 + warp;                 // local 0..63
        int p = blockIdx.x * 64 + row;
        int b = p >> 14;
        const __half2* hb = g_planesh + (size_t)b * HW * 32;
        const __half2* P0 = hb;
        const __half2* P1 = hb + PLANE_H2;
        const __half2* P2 = hb + 2 * PLANE_H2;

        float rc = g_rec[(size_t)p * 32 + lane];

        float px[4], py[4], pz[4], ws[4];
#pragma unroll
        for (int s = 0; s < 4; s++) {
            int smp = 2 * s + hw;
            px[s] = __shfl_sync(0xffffffffu, rc, 3 * smp);
            py[s] = __shfl_sync(0xffffffffu, rc, 3 * smp + 1);
            pz[s] = __shfl_sync(0xffffffffu, rc, 3 * smp + 2);
            ws[s] = __shfl_sync(0xffffffffu, rc, 24 + smp);
        }

        float2 a00 = {0.f, 0.f}, a01 = {0.f, 0.f};
        float2 a10 = {0.f, 0.f}, a11 = {0.f, 0.f};
        float2 a20 = {0.f, 0.f}, a21 = {0.f, 0.f};
#pragma unroll
        for (int s = 0; s < 4; s++) {
            tap4(P0, px[s], pz[s], l16, ws[s], a00, a01);
            tap4(P1, px[s], py[s], l16, ws[s], a10, a11);
            tap4(P2, py[s], pz[s], l16, ws[s], a20, a21);
        }

        a00.x += __shfl_xor_sync(0xffffffffu, a00.x, 16);
        a00.y += __shfl_xor_sync(0xffffffffu, a00.y, 16);
        a01.x += __shfl_xor_sync(0xffffffffu, a01.x, 16);
        a01.y += __shfl_xor_sync(0xffffffffu, a01.y, 16);
        a10.x += __shfl_xor_sync(0xffffffffu, a10.x, 16);
        a10.y += __shfl_xor_sync(0xffffffffu, a10.y, 16);
        a11.x += __shfl_xor_sync(0xffffffffu, a11.x, 16);
        a11.y += __shfl_xor_sync(0xffffffffu, a11.y, 16);
        a20.x += __shfl_xor_sync(0xffffffffu, a20.x, 16);
        a20.y += __shfl_xor_sync(0xffffffffu, a20.y, 16);
        a21.x += __shfl_xor_sync(0xffffffffu, a21.x, 16);
        a21.y += __shfl_xor_sync(0xffffffffu, a21.y, 16);

        if (hw == 0) {
            __half2* arow = &As[row * AS_STRIDE];
            uint2 v0, v1, v2;
            __half2 h;
            h = __floats2half2_rn(a00.x, a00.y); v0.x = *(uint32_t*)&h;
            h = __floats2half2_rn(a01.x, a01.y); v0.y = *(uint32_t*)&h;
            h = __floats2half2_rn(a10.x, a10.y); v1.x = *(uint32_t*)&h;
            h = __floats2half2_rn(a11.x, a11.y); v1.y = *(uint32_t*)&h;
            h = __floats2half2_rn(a20.x, a20.y); v2.x = *(uint32_t*)&h;
            h = __floats2half2_rn(a21.x, a21.y); v2.y = *(uint32_t*)&h;
            *(uint2*)(arow + 2 * l16)      = v0;
            *(uint2*)(arow + 32 + 2 * l16) = v1;
            *(uint2*)(arow + 64 + 2 * l16) = v2;
        }
    }

    asm volatile("cp.async.wait_group 0;");
    __syncthreads();

    // ---- gemm phase: out[64 x 192] += As(64x192) @ M^T ----
    int wm = warp & 3;                   // rows wm*16
    int wn = warp >> 2;                  // cols wn*96
    int g = lane >> 2, t4 = lane & 3;
    int row0 = blockIdx.x * 64;

    float acc[12][4];
#pragma unroll
    for (int i = 0; i < 12; i++)
#pragma unroll
        for (int j = 0; j < 4; j++) acc[i][j] = 0.f;

#pragma unroll
    for (int kt = 0; kt < 12; kt++) {       // 12 k-tiles of 16 halves (8 half2)
        int jb = kt * 8;
        const __half2* arow  = &As[(wm * 16 + g) * AS_STRIDE + jb];
        const __half2* arow8 = &As[(wm * 16 + g + 8) * AS_STRIDE + jb];
        uint32_t a0 = *(const uint32_t*)&arow[t4];
        uint32_t a1 = *(const uint32_t*)&arow8[t4];
        uint32_t a2 = *(const uint32_t*)&arow[t4 + 4];
        uint32_t a3 = *(const uint32_t*)&arow8[t4 + 4];
#pragma unroll
        for (int nt = 0; nt < 12; nt++) {
            int col = wn * 96 + nt * 8 + g;
            uint32_t b0 = *(const uint32_t*)&Bs[col * AS_STRIDE + jb + t4];
            uint32_t b1 = *(const uint32_t*)&Bs[col * AS_STRIDE + jb + t4 + 4];
            asm volatile(
                "mma.sync.aligned.m16n8k16.row.col.f32.f16.f16.f32 "
                "{%0,%1,%2,%3}, {%4,%5,%6,%7}, {%8,%9}, {%0,%1,%2,%3};"
                : "+f"(acc[nt][0]), "+f"(acc[nt][1]),
                  "+f"(acc[nt][2]), "+f"(acc[nt][3])
                : "r"(a0), "r"(a1), "r"(a2), "r"(a3), "r"(b0), "r"(b1));
        }
    }

    int rA = row0 + wm * 16 + g;
#pragma unroll
    for (int nt = 0; nt < 12; nt++) {
        int col = wn * 96 + nt * 8 + t4 * 2;
        float2* p0 = (float2*)(out + (size_t)rA * IND + col);
        float2 v0 = *p0;
        v0.x += acc[nt][0]; v0.y += acc[nt][1];
        *p0 = v0;
        float2* p1 = (float2*)(out + (size_t)(rA + 8) * IND + col);
        float2 v1 = *p1;
        v1.x += acc[nt][2]; v1.y += acc[nt][3];
        *p1 = v1;
    }
}

// ======================= launch ==============================================
extern "C" void kernel_launch(void* const* d_in, const int* in_sizes, int n_in,
                              void* d_out, int out_size) {
    const float* query = (const float*)d_in[0];
    const float* f_xz  = (const float*)d_in[1];
    const float* f_xy  = (const float*)d_in[2];
    const float* f_yz  = (const float*)d_in[3];
    const float* W_v   = (const float*)d_in[4];
    const float* b_v   = (const float*)d_in[5];
    const float* W_out = (const float*)d_in[6];
    const float* b_out = (const float*)d_in[7];
    const float* W_off = (const float*)d_in[8];
    const float* b_off = (const float*)d_in[9];
    const float* W_wt  = (const float*)d_in[10];
    const float* b_wt  = (const float*)d_in[11];
    float* out = (float*)d_out;

    const int gemm_smem = (64 + 192) * AS_STRIDE * 4;   // 102,400 bytes
    cudaFuncSetAttribute(auxgemm_k, cudaFuncAttributeMaxDynamicSharedMemorySize,
                         gemm_smem);

    transpose_k<<<dim3(HW / 32, CPL / 32, 12), dim3(32, 8)>>>(f_xz, f_xy, f_yz);
    prep_k<<<IND, IND>>>(W_v, b_v, W_out);
    featA_k<<<2048, 256>>>(query, W_off, b_off, W_wt, b_wt, b_out, out);
    auxgemm_k<<<NPTS / 64, 256, gemm_smem>>>(out);
}

// round 15
// speedup vs baseline: 1.6210x; 1.0202x over previous
#include <cuda_runtime.h>
#include <cuda_fp16.h>
#include <cstdint>

#define BSZ 4
#define NS  16384
#define SS  8
#define CPL 64
#define RESO 128
#define HW  (RESO*RESO)          // 16384
#define IND 192
#define NPTS (BSZ*NS)            // 65536
#define PLANE_ELEMS (BSZ*HW*CPL) // 4,194,304 per plane
#define PLANE_H2    (PLANE_ELEMS/2)

// ---- device scratch ----
__device__ float   g_planes[3 * PLANE_ELEMS];   // fp32 [pl][b][y][x][c] ~50MB (featA)
__device__ __half2 g_planesh[3 * PLANE_H2];     // fp16 same layout ~25MB (aux)
__device__ float   g_rec[NPTS * 32];            // per-point: 24 pos + 8 weights (8MB)
__device__ __half  g_Mth[IND * IND];            // M[n][k] = (W_out@W_v)[n][k], fp16
__device__ float   g_cb[IND];                   // W_out @ b_v (fp32)

// ======================= K0: transpose -> fp32 + fp16 copies =================
__global__ void transpose_k(const float* __restrict__ p0,
                            const float* __restrict__ p1,
                            const float* __restrict__ p2) {
    __shared__ float tile[32][33];
    int z  = blockIdx.z;          // pl*4 + b
    int pl = z >> 2, b = z & 3;
    const float* src = (pl == 0 ? p0 : (pl == 1 ? p1 : p2)) + (size_t)b * CPL * HW;
    float*   dst  = g_planes  + (size_t)pl * PLANE_ELEMS + (size_t)b * HW * CPL;
    __half2* dst2 = g_planesh + (size_t)pl * PLANE_H2    + (size_t)b * HW * 32;
    int hw0 = blockIdx.x * 32;
    int c0  = blockIdx.y * 32;
    int tx = threadIdx.x, ty = threadIdx.y;
#pragma unroll
    for (int j = 0; j < 32; j += 8)
        tile[ty + j][tx] = src[(size_t)(c0 + ty + j) * HW + hw0 + tx];
    __syncthreads();
#pragma unroll
    for (int j = 0; j < 32; j += 8)
        dst[(size_t)(hw0 + ty + j) * CPL + c0 + tx] = tile[tx][ty + j];
    if (tx < 16) {
#pragma unroll
        for (int j = 0; j < 32; j += 8) {
            int r = ty + j;
            __half2 hv = __floats2half2_rn(tile[2 * tx][r], tile[2 * tx + 1][r]);
            dst2[(size_t)(hw0 + r) * 32 + (c0 >> 1) + tx] = hv;
        }
    }
}

// ======================= K1: fold weights -> fp16 M ==========================
__global__ void prep_k(const float* __restrict__ W_v,
                       const float* __restrict__ b_v,
                       const float* __restrict__ W_out) {
    int n = blockIdx.x;
    int k = threadIdx.x;
    float acc = 0.f;
#pragma unroll 4
    for (int j = 0; j < IND; j++)
        acc = fmaf(W_out[n * IND + j], W_v[j * IND + k], acc);
    g_Mth[n * IND + k] = __float2half(acc);
    if (k == 0) {
        float c = 0.f;
        for (int j = 0; j < IND; j++) c = fmaf(W_out[n * IND + j], b_v[j], c);
        g_cb[n] = c;
    }
}

// ======================= fp32 bilinear tap (2 ch / lane) =====================
__device__ __forceinline__ float2 samp2f(const float* __restrict__ pb,
                                         float u, float v, int c) {
    float x = __saturatef(u) * 127.0f;
    float y = __saturatef(v) * 127.0f;
    float xf = floorf(x), yf = floorf(y);
    int x0 = (int)xf, y0 = (int)yf;
    int x1 = min(x0 + 1, 127), y1 = min(y0 + 1, 127);
    float wx = x - xf, wy = y - yf;
    float2 f00 = *(const float2*)(pb + (((y0 << 7) + x0) << 6) + c);
    float2 f01 = *(const float2*)(pb + (((y0 << 7) + x1) << 6) + c);
    float2 f10 = *(const float2*)(pb + (((y1 << 7) + x0) << 6) + c);
    float2 f11 = *(const float2*)(pb + (((y1 << 7) + x1) << 6) + c);
    float w00 = (1.f - wx) * (1.f - wy), w01 = wx * (1.f - wy);
    float w10 = (1.f - wx) * wy,        w11 = wx * wy;
    float2 r;
    r.x = f00.x * w00 + f01.x * w01 + f10.x * w10 + f11.x * w11;
    r.y = f00.y * w00 + f01.y * w01 + f10.y * w10 + f11.y * w11;
    return r;
}

// ======================= K2a: query feature + offsets + residual =============
#define WS_STRIDE 196
__global__ __launch_bounds__(256) void featA_k(
    const float* __restrict__ query,
    const float* __restrict__ W_off, const float* __restrict__ b_off,
    const float* __restrict__ W_wt,  const float* __restrict__ b_wt,
    const float* __restrict__ b_out, float* __restrict__ out) {

    __shared__ float Wsh[32 * WS_STRIDE];   // rows 0..23 W_off, 24..31 W_wt
    __shared__ float feat[32][IND];         // row = warp*4 + j

    for (int i = threadIdx.x; i < 32 * IND; i += 256) {
        int row = i / IND, col = i % IND;
        float w = (row < 24) ? W_off[row * IND + col] : W_wt[(row - 24) * IND + col];
        Wsh[row * WS_STRIDE + col] = w;
    }
    __syncthreads();

    const int warp = threadIdx.x >> 5;
    const int lane = threadIdx.x & 31;
    const int c = lane * 2;

    const float bias = (lane < 24) ? b_off[lane] : b_wt[lane - 24];
    const float2 cb0 = *(const float2*)(g_cb + c);
    const float2 cb1 = *(const float2*)(g_cb + 64 + c);
    const float2 cb2 = *(const float2*)(g_cb + 128 + c);
    const float2 bo0 = *(const float2*)(b_out + c);
    const float2 bo1 = *(const float2*)(b_out + 64 + c);
    const float2 bo2 = *(const float2*)(b_out + 128 + c);

    const int pbase = blockIdx.x * 32 + warp * 4;

    // ---- taps: 4 points ----
    float2 fr[4][3];
    float  qv[4][3];
#pragma unroll
    for (int j = 0; j < 4; j++) {
        int p = pbase + j;
        int b = p >> 14;
        const float* fb = g_planes + (size_t)b * HW * CPL;
        const float* F0 = fb;
        const float* F1 = fb + PLANE_ELEMS;
        const float* F2 = fb + 2 * PLANE_ELEMS;

        float qx = query[p * 3 + 0];
        float qy = query[p * 3 + 1];
        float qz = query[p * 3 + 2];
        qv[j][0] = qx; qv[j][1] = qy; qv[j][2] = qz;

        float2 f0 = samp2f(F0, qx, qz, c);
        float2 f1 = samp2f(F1, qx, qy, c);
        float2 f2 = samp2f(F2, qy, qz, c);
        fr[j][0] = f0; fr[j][1] = f1; fr[j][2] = f2;
        int row = warp * 4 + j;
        feat[row][c]           = f0.x; feat[row][c + 1]       = f0.y;
        feat[row][64 + c]      = f1.x; feat[row][64 + c + 1]  = f1.y;
        feat[row][128 + c]     = f2.x; feat[row][128 + c + 1] = f2.y;
    }
    __syncwarp();

    // ---- batched GEMV: 1 W pass for 4 points ----
    float o[4] = {bias, bias, bias, bias};
    const float* wrow = &Wsh[lane * WS_STRIDE];
    const float* f0r = feat[warp * 4 + 0];
    const float* f1r = feat[warp * 4 + 1];
    const float* f2r = feat[warp * 4 + 2];
    const float* f3r = feat[warp * 4 + 3];
#pragma unroll 6
    for (int k = 0; k < IND; k += 4) {
        float4 w = *(const float4*)(wrow + k);
        float4 a = *(const float4*)(f0r + k);
        float4 bq = *(const float4*)(f1r + k);
        float4 cq = *(const float4*)(f2r + k);
        float4 d = *(const float4*)(f3r + k);
        o[0] = fmaf(a.x,  w.x, fmaf(a.y,  w.y, fmaf(a.z,  w.z, fmaf(a.w,  w.w, o[0]))));
        o[1] = fmaf(bq.x, w.x, fmaf(bq.y, w.y, fmaf(bq.z, w.z, fmaf(bq.w, w.w, o[1]))));
        o[2] = fmaf(cq.x, w.x, fmaf(cq.y, w.y, fmaf(cq.z, w.z, fmaf(cq.w, w.w, o[2]))));
        o[3] = fmaf(d.x,  w.x, fmaf(d.y,  w.y, fmaf(d.z,  w.z, fmaf(d.w,  w.w, o[3]))));
    }

    // ---- per-point epilogue ----
#pragma unroll
    for (int j = 0; j < 4; j++) {
        int p = pbase + j;
        float oj = o[j];

        float wv = (lane >= 24) ? oj : 0.f;
#pragma unroll
        for (int d = 16; d; d >>= 1) wv += __shfl_xor_sync(0xffffffffu, wv, d);

        float rc;
        if (lane < 24) {
            int d3 = lane - (lane / 3) * 3;
            rc = oj + qv[j][d3];
        } else {
            rc = oj;
        }
        __stwt(&g_rec[(size_t)p * 32 + lane], rc);

        float2 f0 = fr[j][0], f1 = fr[j][1], f2 = fr[j][2];
        float* orow = out + (size_t)p * IND;
        __stwt((float2*)(orow + c),
               make_float2(f0.x + wv * cb0.x + bo0.x, f0.y + wv * cb0.y + bo0.y));
        __stwt((float2*)(orow + 64 + c),
               make_float2(f1.x + wv * cb1.x + bo1.x, f1.y + wv * cb1.y + bo1.y));
        __stwt((float2*)(orow + 128 + c),
               make_float2(f2.x + wv * cb2.x + bo2.x, f2.y + wv * cb2.y + bo2.y));
    }
}

// ======================= K2b+K3 fused: aux gather + gemm =====================
__device__ __forceinline__ void tap4(const __half2* __restrict__ pb,
                                     float u, float v, int l16, float ws,
                                     float2& acc0, float2& acc1) {
    float x = __saturatef(u) * 127.0f;
    float y = __saturatef(v) * 127.0f;
    float xf = floorf(x), yf = floorf(y);
    int x0 = (int)xf, y0 = (int)yf;
    int x1 = min(x0 + 1, 127), y1 = min(y0 + 1, 127);
    float wx = x - xf, wy = y - yf;
    const __half2* pl = pb + 2 * l16;
    uint2 f00 = *(const uint2*)(pl + (((y0 << 7) + x0) << 5));
    uint2 f01 = *(const uint2*)(pl + (((y0 << 7) + x1) << 5));
    uint2 f10 = *(const uint2*)(pl + (((y1 << 7) + x0) << 5));
    uint2 f11 = *(const uint2*)(pl + (((y1 << 7) + x1) << 5));
    float w00 = (1.f - wx) * (1.f - wy), w01 = wx * (1.f - wy);
    float w10 = (1.f - wx) * wy,        w11 = wx * wy;
    float ww00 = ws * w00, ww01 = ws * w01, ww10 = ws * w10, ww11 = ws * w11;
    float2 c00 = __half22float2(*(const __half2*)&f00.x);
    float2 c01 = __half22float2(*(const __half2*)&f01.x);
    float2 c10 = __half22float2(*(const __half2*)&f10.x);
    float2 c11 = __half22float2(*(const __half2*)&f11.x);
    acc0.x = fmaf(ww00, c00.x, fmaf(ww01, c01.x, fmaf(ww10, c10.x, fmaf(ww11, c11.x, acc0.x))));
    acc0.y = fmaf(ww00, c00.y, fmaf(ww01, c01.y, fmaf(ww10, c10.y, fmaf(ww11, c11.y, acc0.y))));
    float2 d00 = __half22float2(*(const __half2*)&f00.y);
    float2 d01 = __half22float2(*(const __half2*)&f01.y);
    float2 d10 = __half22float2(*(const __half2*)&f10.y);
    float2 d11 = __half22float2(*(const __half2*)&f11.y);
    acc1.x = fmaf(ww00, d00.x, fmaf(ww01, d01.x, fmaf(ww10, d10.x, fmaf(ww11, d11.x, acc1.x))));
    acc1.y = fmaf(ww00, d00.y, fmaf(ww01, d01.y, fmaf(ww10, d10.y, fmaf(ww11, d11.y, acc1.y))));
}

__device__ __forceinline__ void cp16(uint32_t smem, const void* gmem) {
    asm volatile("cp.async.ca.shared.global [%0], [%1], 16;"
                 :: "r"(smem), "l"(gmem));
}

// smem: As [64][100] half2 (25.6KB) + Bst [2][192*12] half2 (18.4KB) = 44KB
#define AS_STRIDE 100
#define B_STRIDE  12
#define B_TILE    (IND * B_STRIDE)      // 2304 half2 per buffer
#define AUXG_SMEM ((64 * AS_STRIDE + 2 * B_TILE) * 4)

__global__ __launch_bounds__(256, 3) void auxgemm_k(float* __restrict__ out) {
    extern __shared__ __half2 sm[];
    __half2* As  = sm;                     // [64][100]  agg tile (built in-place)
    __half2* Bst = sm + 64 * AS_STRIDE;    // [2][192][12] streamed M k-tiles

    int t = threadIdx.x;
    int warp = t >> 5, lane = t & 31;
    int hw = lane >> 4, l16 = lane & 15;

    // ---- B-tile loader: k-tile kt (16 halves) for all 192 n-rows ----
    // 384 cp16 per tile: idx -> col=idx>>1, half=idx&1
    auto load_btile = [&](int kt, int buf) {
        const __half* src = g_Mth + kt * 16;
        __half2* dstb = Bst + buf * B_TILE;
        {
            int col = t >> 1, half = t & 1;
            cp16((uint32_t)__cvta_generic_to_shared(&dstb[col * B_STRIDE + half * 4]),
                 src + col * IND + half * 8);
        }
        if (t < 128) {
            int idx = 256 + t;
            int col = idx >> 1, half = idx & 1;
            cp16((uint32_t)__cvta_generic_to_shared(&dstb[col * B_STRIDE + half * 4]),
                 src + col * IND + half * 8);
        }
        asm volatile("cp.async.commit_group;");
    };

    // prologue: tiles 0,1 in flight — they arrive during the aux phase
    load_btile(0, 0);
    load_btile(1, 1);

    // ---- aux phase: 64 points per block, 8 per warp ----
    for (int it = 0; it < 8; ++it) {
        int row = it * 8 + warp;                 // local 0..63
        int p = blockIdx.x * 64 + row;
        int b = p >> 14;
        const __half2* hb = g_planesh + (size_t)b * HW * 32;
        const __half2* P0 = hb;
        const __half2* P1 = hb + PLANE_H2;
        const __half2* P2 = hb + 2 * PLANE_H2;

        float rc = g_rec[(size_t)p * 32 + lane];

        float px[4], py[4], pz[4], ws[4];
#pragma unroll
        for (int s = 0; s < 4; s++) {
            int smp = 2 * s + hw;
            px[s] = __shfl_sync(0xffffffffu, rc, 3 * smp);
            py[s] = __shfl_sync(0xffffffffu, rc, 3 * smp + 1);
            pz[s] = __shfl_sync(0xffffffffu, rc, 3 * smp + 2);
            ws[s] = __shfl_sync(0xffffffffu, rc, 24 + smp);
        }

        float2 a00 = {0.f, 0.f}, a01 = {0.f, 0.f};
        float2 a10 = {0.f, 0.f}, a11 = {0.f, 0.f};
        float2 a20 = {0.f, 0.f}, a21 = {0.f, 0.f};
#pragma unroll
        for (int s = 0; s < 4; s++) {
            tap4(P0, px[s], pz[s], l16, ws[s], a00, a01);
            tap4(P1, px[s], py[s], l16, ws[s], a10, a11);
            tap4(P2, py[s], pz[s], l16, ws[s], a20, a21);
        }

        a00.x += __shfl_xor_sync(0xffffffffu, a00.x, 16);
        a00.y += __shfl_xor_sync(0xffffffffu, a00.y, 16);
        a01.x += __shfl_xor_sync(0xffffffffu, a01.x, 16);
        a01.y += __shfl_xor_sync(0xffffffffu, a01.y, 16);
        a10.x += __shfl_xor_sync(0xffffffffu, a10.x, 16);
        a10.y += __shfl_xor_sync(0xffffffffu, a10.y, 16);
        a11.x += __shfl_xor_sync(0xffffffffu, a11.x, 16);
        a11.y += __shfl_xor_sync(0xffffffffu, a11.y, 16);
        a20.x += __shfl_xor_sync(0xffffffffu, a20.x, 16);
        a20.y += __shfl_xor_sync(0xffffffffu, a20.y, 16);
        a21.x += __shfl_xor_sync(0xffffffffu, a21.x, 16);
        a21.y += __shfl_xor_sync(0xffffffffu, a21.y, 16);

        if (hw == 0) {
            __half2* arow = &As[row * AS_STRIDE];
            uint2 v0, v1, v2;
            __half2 h;
            h = __floats2half2_rn(a00.x, a00.y); v0.x = *(uint32_t*)&h;
            h = __floats2half2_rn(a01.x, a01.y); v0.y = *(uint32_t*)&h;
            h = __floats2half2_rn(a10.x, a10.y); v1.x = *(uint32_t*)&h;
            h = __floats2half2_rn(a11.x, a11.y); v1.y = *(uint32_t*)&h;
            h = __floats2half2_rn(a20.x, a20.y); v2.x = *(uint32_t*)&h;
            h = __floats2half2_rn(a21.x, a21.y); v2.y = *(uint32_t*)&h;
            *(uint2*)(arow + 2 * l16)      = v0;
            *(uint2*)(arow + 32 + 2 * l16) = v1;
            *(uint2*)(arow + 64 + 2 * l16) = v2;
        }
    }

    // ---- gemm phase: out[64 x 192] += As(64x192) @ M^T, B double-buffered ----
    int wm = warp & 3;                   // rows wm*16
    int wn = warp >> 2;                  // cols wn*96
    int g = lane >> 2, t4 = lane & 3;
    int row0 = blockIdx.x * 64;

    float acc[12][4];
#pragma unroll
    for (int i = 0; i < 12; i++)
#pragma unroll
        for (int j = 0; j < 4; j++) acc[i][j] = 0.f;

#pragma unroll
    for (int kt = 0; kt < 12; kt++) {
        if (kt < 11) {
            asm volatile("cp.async.wait_group 1;");
        } else {
            asm volatile("cp.async.wait_group 0;");
        }
        __syncthreads();        // tile kt visible to all; As ready (kt==0)

        int jb = kt * 8;
        const __half2* bbase = Bst + (kt & 1) * B_TILE;
        const __half2* arow  = &As[(wm * 16 + g) * AS_STRIDE + jb];
        const __half2* arow8 = &As[(wm * 16 + g + 8) * AS_STRIDE + jb];
        uint32_t a0 = *(const uint32_t*)&arow[t4];
        uint32_t a1 = *(const uint32_t*)&arow8[t4];
        uint32_t a2 = *(const uint32_t*)&arow[t4 + 4];
        uint32_t a3 = *(const uint32_t*)&arow8[t4 + 4];
#pragma unroll
        for (int nt = 0; nt < 12; nt++) {
            int col = wn * 96 + nt * 8 + g;
            uint32_t b0 = *(const uint32_t*)&bbase[col * B_STRIDE + t4];
            uint32_t b1 = *(const uint32_t*)&bbase[col * B_STRIDE + t4 + 4];
            asm volatile(
                "mma.sync.aligned.m16n8k16.row.col.f32.f16.f16.f32 "
                "{%0,%1,%2,%3}, {%4,%5,%6,%7}, {%8,%9}, {%0,%1,%2,%3};"
                : "+f"(acc[nt][0]), "+f"(acc[nt][1]),
                  "+f"(acc[nt][2]), "+f"(acc[nt][3])
                : "r"(a0), "r"(a1), "r"(a2), "r"(a3), "r"(b0), "r"(b1));
        }

        __syncthreads();        // all warps done reading buf kt&1
        if (kt < 10) load_btile(kt + 2, kt & 1);
    }

    int rA = row0 + wm * 16 + g;
#pragma unroll
    for (int nt = 0; nt < 12; nt++) {
        int col = wn * 96 + nt * 8 + t4 * 2;
        float2* p0 = (float2*)(out + (size_t)rA * IND + col);
        float2 v0 = *p0;
        v0.x += acc[nt][0]; v0.y += acc[nt][1];
        *p0 = v0;
        float2* p1 = (float2*)(out + (size_t)(rA + 8) * IND + col);
        float2 v1 = *p1;
        v1.x += acc[nt][2]; v1.y += acc[nt][3];
        *p1 = v1;
    }
}

// ======================= launch ==============================================
extern "C" void kernel_launch(void* const* d_in, const int* in_sizes, int n_in,
                              void* d_out, int out_size) {
    const float* query = (const float*)d_in[0];
    const float* f_xz  = (const float*)d_in[1];
    const float* f_xy  = (const float*)d_in[2];
    const float* f_yz  = (const float*)d_in[3];
    const float* W_v   = (const float*)d_in[4];
    const float* b_v   = (const float*)d_in[5];
    const float* W_out = (const float*)d_in[6];
    const float* b_out = (const float*)d_in[7];
    const float* W_off = (const float*)d_in[8];
    const float* b_off = (const float*)d_in[9];
    const float* W_wt  = (const float*)d_in[10];
    const float* b_wt  = (const float*)d_in[11];
    float* out = (float*)d_out;

    cudaFuncSetAttribute(auxgemm_k, cudaFuncAttributeMaxDynamicSharedMemorySize,
                         AUXG_SMEM);

    transpose_k<<<dim3(HW / 32, CPL / 32, 12), dim3(32, 8)>>>(f_xz, f_xy, f_yz);
    prep_k<<<IND, IND>>>(W_v, b_v, W_out);
    featA_k<<<2048, 256>>>(query, W_off, b_off, W_wt, b_wt, b_out, out);
    auxgemm_k<<<NPTS / 64, 256, AUXG_SMEM>>>(out);
}

// round 16
// speedup vs baseline: 1.7540x; 1.0820x over previous
#include <cuda_runtime.h>
#include <cuda_fp16.h>
#include <cstdint>

#define BSZ 4
#define NS  16384
#define SS  8
#define CPL 64
#define RESO 128
#define HW  (RESO*RESO)          // 16384
#define IND 192
#define NPTS (BSZ*NS)            // 65536
#define PLANE_ELEMS (BSZ*HW*CPL) // 4,194,304 per plane
#define PLANE_H2    (PLANE_ELEMS/2)

// ---- device scratch ----
__device__ float   g_planes[3 * PLANE_ELEMS];   // fp32 [pl][b][y][x][c] ~50MB (featA)
__device__ __half2 g_planesh[3 * PLANE_H2];     // fp16 same layout ~25MB (aux)
__device__ float   g_rec[NPTS * 32];            // per-point: 24 pos + 8 weights (8MB)
__device__ __half  g_Mth[IND * IND];            // M[n][k] = (W_out@W_v)[n][k], fp16
__device__ float   g_cb[IND];                   // W_out @ b_v (fp32)

// ======================= K0: transpose -> fp32 + fp16 copies =================
__global__ void transpose_k(const float* __restrict__ p0,
                            const float* __restrict__ p1,
                            const float* __restrict__ p2) {
    __shared__ float tile[32][33];
    int z  = blockIdx.z;          // pl*4 + b
    int pl = z >> 2, b = z & 3;
    const float* src = (pl == 0 ? p0 : (pl == 1 ? p1 : p2)) + (size_t)b * CPL * HW;
    float*   dst  = g_planes  + (size_t)pl * PLANE_ELEMS + (size_t)b * HW * CPL;
    __half2* dst2 = g_planesh + (size_t)pl * PLANE_H2    + (size_t)b * HW * 32;
    int hw0 = blockIdx.x * 32;
    int c0  = blockIdx.y * 32;
    int tx = threadIdx.x, ty = threadIdx.y;
#pragma unroll
    for (int j = 0; j < 32; j += 8)
        tile[ty + j][tx] = src[(size_t)(c0 + ty + j) * HW + hw0 + tx];
    __syncthreads();
#pragma unroll
    for (int j = 0; j < 32; j += 8)
        dst[(size_t)(hw0 + ty + j) * CPL + c0 + tx] = tile[tx][ty + j];
    if (tx < 16) {
#pragma unroll
        for (int j = 0; j < 32; j += 8) {
            int r = ty + j;
            __half2 hv = __floats2half2_rn(tile[2 * tx][r], tile[2 * tx + 1][r]);
            dst2[(size_t)(hw0 + r) * 32 + (c0 >> 1) + tx] = hv;
        }
    }
}

// ======================= K1: fold weights -> fp16 M ==========================
__global__ void prep_k(const float* __restrict__ W_v,
                       const float* __restrict__ b_v,
                       const float* __restrict__ W_out) {
    int n = blockIdx.x;
    int k = threadIdx.x;
    float acc = 0.f;
#pragma unroll 4
    for (int j = 0; j < IND; j++)
        acc = fmaf(W_out[n * IND + j], W_v[j * IND + k], acc);
    g_Mth[n * IND + k] = __float2half(acc);
    if (k == 0) {
        float c = 0.f;
        for (int j = 0; j < IND; j++) c = fmaf(W_out[n * IND + j], b_v[j], c);
        g_cb[n] = c;
    }
}

// ======================= fp32 bilinear tap (2 ch / lane) =====================
__device__ __forceinline__ float2 samp2f(const float* __restrict__ pb,
                                         float u, float v, int c) {
    float x = __saturatef(u) * 127.0f;
    float y = __saturatef(v) * 127.0f;
    float xf = floorf(x), yf = floorf(y);
    int x0 = (int)xf, y0 = (int)yf;
    int x1 = min(x0 + 1, 127), y1 = min(y0 + 1, 127);
    float wx = x - xf, wy = y - yf;
    float2 f00 = *(const float2*)(pb + (((y0 << 7) + x0) << 6) + c);
    float2 f01 = *(const float2*)(pb + (((y0 << 7) + x1) << 6) + c);
    float2 f10 = *(const float2*)(pb + (((y1 << 7) + x0) << 6) + c);
    float2 f11 = *(const float2*)(pb + (((y1 << 7) + x1) << 6) + c);
    float w00 = (1.f - wx) * (1.f - wy), w01 = wx * (1.f - wy);
    float w10 = (1.f - wx) * wy,        w11 = wx * wy;
    float2 r;
    r.x = f00.x * w00 + f01.x * w01 + f10.x * w10 + f11.x * w11;
    r.y = f00.y * w00 + f01.y * w01 + f10.y * w10 + f11.y * w11;
    return r;
}

// ======================= K2a: query feature + offsets + residual =============
#define WS_STRIDE 196
__global__ __launch_bounds__(256) void featA_k(
    const float* __restrict__ query,
    const float* __restrict__ W_off, const float* __restrict__ b_off,
    const float* __restrict__ W_wt,  const float* __restrict__ b_wt,
    const float* __restrict__ b_out, float* __restrict__ out) {

    __shared__ float Wsh[32 * WS_STRIDE];   // rows 0..23 W_off, 24..31 W_wt
    __shared__ float feat[32][IND];         // row = warp*4 + j

    for (int i = threadIdx.x; i < 32 * IND; i += 256) {
        int row = i / IND, col = i % IND;
        float w = (row < 24) ? W_off[row * IND + col] : W_wt[(row - 24) * IND + col];
        Wsh[row * WS_STRIDE + col] = w;
    }
    __syncthreads();

    const int warp = threadIdx.x >> 5;
    const int lane = threadIdx.x & 31;
    const int c = lane * 2;

    const float bias = (lane < 24) ? b_off[lane] : b_wt[lane - 24];
    const float2 cb0 = *(const float2*)(g_cb + c);
    const float2 cb1 = *(const float2*)(g_cb + 64 + c);
    const float2 cb2 = *(const float2*)(g_cb + 128 + c);
    const float2 bo0 = *(const float2*)(b_out + c);
    const float2 bo1 = *(const float2*)(b_out + 64 + c);
    const float2 bo2 = *(const float2*)(b_out + 128 + c);

    const int pbase = blockIdx.x * 32 + warp * 4;

    // ---- taps: 4 points ----
    float2 fr[4][3];
    float  qv[4][3];
#pragma unroll
    for (int j = 0; j < 4; j++) {
        int p = pbase + j;
        int b = p >> 14;
        const float* fb = g_planes + (size_t)b * HW * CPL;
        const float* F0 = fb;
        const float* F1 = fb + PLANE_ELEMS;
        const float* F2 = fb + 2 * PLANE_ELEMS;

        float qx = query[p * 3 + 0];
        float qy = query[p * 3 + 1];
        float qz = query[p * 3 + 2];
        qv[j][0] = qx; qv[j][1] = qy; qv[j][2] = qz;

        float2 f0 = samp2f(F0, qx, qz, c);
        float2 f1 = samp2f(F1, qx, qy, c);
        float2 f2 = samp2f(F2, qy, qz, c);
        fr[j][0] = f0; fr[j][1] = f1; fr[j][2] = f2;
        int row = warp * 4 + j;
        feat[row][c]           = f0.x; feat[row][c + 1]       = f0.y;
        feat[row][64 + c]      = f1.x; feat[row][64 + c + 1]  = f1.y;
        feat[row][128 + c]     = f2.x; feat[row][128 + c + 1] = f2.y;
    }
    __syncwarp();

    // ---- batched GEMV: 1 W pass for 4 points ----
    float o[4] = {bias, bias, bias, bias};
    const float* wrow = &Wsh[lane * WS_STRIDE];
    const float* f0r = feat[warp * 4 + 0];
    const float* f1r = feat[warp * 4 + 1];
    const float* f2r = feat[warp * 4 + 2];
    const float* f3r = feat[warp * 4 + 3];
#pragma unroll 6
    for (int k = 0; k < IND; k += 4) {
        float4 w = *(const float4*)(wrow + k);
        float4 a = *(const float4*)(f0r + k);
        float4 bq = *(const float4*)(f1r + k);
        float4 cq = *(const float4*)(f2r + k);
        float4 d = *(const float4*)(f3r + k);
        o[0] = fmaf(a.x,  w.x, fmaf(a.y,  w.y, fmaf(a.z,  w.z, fmaf(a.w,  w.w, o[0]))));
        o[1] = fmaf(bq.x, w.x, fmaf(bq.y, w.y, fmaf(bq.z, w.z, fmaf(bq.w, w.w, o[1]))));
        o[2] = fmaf(cq.x, w.x, fmaf(cq.y, w.y, fmaf(cq.z, w.z, fmaf(cq.w, w.w, o[2]))));
        o[3] = fmaf(d.x,  w.x, fmaf(d.y,  w.y, fmaf(d.z,  w.z, fmaf(d.w,  w.w, o[3]))));
    }

    // ---- per-point epilogue ----
#pragma unroll
    for (int j = 0; j < 4; j++) {
        int p = pbase + j;
        float oj = o[j];

        float wv = (lane >= 24) ? oj : 0.f;
#pragma unroll
        for (int d = 16; d; d >>= 1) wv += __shfl_xor_sync(0xffffffffu, wv, d);

        float rc;
        if (lane < 24) {
            int d3 = lane - (lane / 3) * 3;
            rc = oj + qv[j][d3];
        } else {
            rc = oj;
        }
        __stwt(&g_rec[(size_t)p * 32 + lane], rc);

        float2 f0 = fr[j][0], f1 = fr[j][1], f2 = fr[j][2];
        float* orow = out + (size_t)p * IND;
        __stwt((float2*)(orow + c),
               make_float2(f0.x + wv * cb0.x + bo0.x, f0.y + wv * cb0.y + bo0.y));
        __stwt((float2*)(orow + 64 + c),
               make_float2(f1.x + wv * cb1.x + bo1.x, f1.y + wv * cb1.y + bo1.y));
        __stwt((float2*)(orow + 128 + c),
               make_float2(f2.x + wv * cb2.x + bo2.x, f2.y + wv * cb2.y + bo2.y));
    }
}

// ======================= K2b+K3 fused: aux gather + gemm =====================
// 8-channel fp16 tap: one uint4 per corner, HFMA2 blend into 4 half2 accums.
__device__ __forceinline__ void tap8(const __half2* __restrict__ pb,
                                     float u, float v, int co, float ws,
                                     __half2* acc) {
    float x = __saturatef(u) * 127.0f;
    float y = __saturatef(v) * 127.0f;
    float xf = floorf(x), yf = floorf(y);
    int x0 = (int)xf, y0 = (int)yf;
    int x1 = min(x0 + 1, 127), y1 = min(y0 + 1, 127);
    float wx = x - xf, wy = y - yf;
    float w00 = (1.f - wx) * (1.f - wy), w01 = wx * (1.f - wy);
    float w10 = (1.f - wx) * wy,        w11 = wx * wy;
    __half2 h00 = __float2half2_rn(ws * w00);
    __half2 h01 = __float2half2_rn(ws * w01);
    __half2 h10 = __float2half2_rn(ws * w10);
    __half2 h11 = __float2half2_rn(ws * w11);
    uint4 v00 = *(const uint4*)(pb + ((((y0 << 7) + x0) << 5) + co));
    uint4 v01 = *(const uint4*)(pb + ((((y0 << 7) + x1) << 5) + co));
    uint4 v10 = *(const uint4*)(pb + ((((y1 << 7) + x0) << 5) + co));
    uint4 v11 = *(const uint4*)(pb + ((((y1 << 7) + x1) << 5) + co));
#pragma unroll
    for (int i = 0; i < 4; i++) {
        acc[i] = __hfma2(h00, ((const __half2*)&v00)[i], acc[i]);
        acc[i] = __hfma2(h01, ((const __half2*)&v01)[i], acc[i]);
        acc[i] = __hfma2(h10, ((const __half2*)&v10)[i], acc[i]);
        acc[i] = __hfma2(h11, ((const __half2*)&v11)[i], acc[i]);
    }
}

__device__ __forceinline__ void cp16(uint32_t smem, const void* gmem) {
    asm volatile("cp.async.ca.shared.global [%0], [%1], 16;"
                 :: "r"(smem), "l"(gmem));
}

// smem: As [64][100] half2 (25.6KB) + Bst [2][192*12] half2 (18.4KB) = 44KB
#define AS_STRIDE 100
#define B_STRIDE  12
#define B_TILE    (IND * B_STRIDE)      // 2304 half2 per buffer
#define AUXG_SMEM ((64 * AS_STRIDE + 2 * B_TILE) * 4)

__global__ __launch_bounds__(256, 3) void auxgemm_k(float* __restrict__ out) {
    extern __shared__ __half2 sm[];
    __half2* As  = sm;                     // [64][100]  agg tile (built in-place)
    __half2* Bst = sm + 64 * AS_STRIDE;    // [2][192][12] streamed M k-tiles

    int t = threadIdx.x;
    int warp = t >> 5, lane = t & 31;
    int s4 = lane >> 3, c8 = lane & 7;
    int co = c8 * 4;                       // half2 offset within texel

    // ---- B-tile loader: k-tile kt (16 halves) for all 192 n-rows ----
    auto load_btile = [&](int kt, int buf) {
        const __half* src = g_Mth + kt * 16;
        __half2* dstb = Bst + buf * B_TILE;
        {
            int col = t >> 1, half = t & 1;
            cp16((uint32_t)__cvta_generic_to_shared(&dstb[col * B_STRIDE + half * 4]),
                 src + col * IND + half * 8);
        }
        if (t < 128) {
            int idx = 256 + t;
            int col = idx >> 1, half = idx & 1;
            cp16((uint32_t)__cvta_generic_to_shared(&dstb[col * B_STRIDE + half * 4]),
                 src + col * IND + half * 8);
        }
        asm volatile("cp.async.commit_group;");
    };

    // prologue: tiles 0,1 in flight — they arrive during the aux phase
    load_btile(0, 0);
    load_btile(1, 1);

    // ---- aux phase: 64 points per block, 8 per warp ----
    for (int it = 0; it < 8; ++it) {
        int row = it * 8 + warp;                 // local 0..63
        int p = blockIdx.x * 64 + row;
        int b = p >> 14;
        const __half2* hb = g_planesh + (size_t)b * HW * 32;
        const __half2* P0 = hb;
        const __half2* P1 = hb + PLANE_H2;
        const __half2* P2 = hb + 2 * PLANE_H2;

        float rc = g_rec[(size_t)p * 32 + lane];

        __half2 acc[12];
        __half2 zz = __floats2half2_rn(0.f, 0.f);
#pragma unroll
        for (int i = 0; i < 12; i++) acc[i] = zz;

#pragma unroll
        for (int rep = 0; rep < 2; rep++) {
            int smp = s4 + rep * 4;     // this lane-group's sample
            float px = __shfl_sync(0xffffffffu, rc, 3 * smp);
            float py = __shfl_sync(0xffffffffu, rc, 3 * smp + 1);
            float pz = __shfl_sync(0xffffffffu, rc, 3 * smp + 2);
            float ws = __shfl_sync(0xffffffffu, rc, 24 + smp);
            tap8(P0, px, pz, co, ws, acc + 0);
            tap8(P1, px, py, co, ws, acc + 4);
            tap8(P2, py, pz, co, ws, acc + 8);
        }

        // reduce across the 4 sample-groups (lane bits 3,4)
#pragma unroll
        for (int i = 0; i < 12; i++) {
            uint32_t u = *(uint32_t*)&acc[i];
            uint32_t o8 = __shfl_xor_sync(0xffffffffu, u, 8);
            acc[i] = __hadd2(acc[i], *(__half2*)&o8);
            u = *(uint32_t*)&acc[i];
            uint32_t o16 = __shfl_xor_sync(0xffffffffu, u, 16);
            acc[i] = __hadd2(acc[i], *(__half2*)&o16);
        }

        if (lane < 8) {       // s4 == 0 group stores; lane c8 owns channels 8c8..8c8+7
            __half2* arow = &As[row * AS_STRIDE + co];
            uint4 st;
            st.x = *(uint32_t*)&acc[0]; st.y = *(uint32_t*)&acc[1];
            st.z = *(uint32_t*)&acc[2]; st.w = *(uint32_t*)&acc[3];
            *(uint4*)(arow) = st;
            st.x = *(uint32_t*)&acc[4]; st.y = *(uint32_t*)&acc[5];
            st.z = *(uint32_t*)&acc[6]; st.w = *(uint32_t*)&acc[7];
            *(uint4*)(arow + 32) = st;
            st.x = *(uint32_t*)&acc[8]; st.y = *(uint32_t*)&acc[9];
            st.z = *(uint32_t*)&acc[10]; st.w = *(uint32_t*)&acc[11];
            *(uint4*)(arow + 64) = st;
        }
    }

    // ---- gemm phase: out[64 x 192] += As(64x192) @ M^T, B double-buffered ----
    int wm = warp & 3;                   // rows wm*16
    int wn = warp >> 2;                  // cols wn*96
    int g = lane >> 2, t4 = lane & 3;
    int row0 = blockIdx.x * 64;

    float acc[12][4];
#pragma unroll
    for (int i = 0; i < 12; i++)
#pragma unroll
        for (int j = 0; j < 4; j++) acc[i][j] = 0.f;

#pragma unroll
    for (int kt = 0; kt < 12; kt++) {
        if (kt < 11) {
            asm volatile("cp.async.wait_group 1;");
        } else {
            asm volatile("cp.async.wait_group 0;");
        }
        __syncthreads();        // tile kt visible to all; As ready (kt==0)

        int jb = kt * 8;
        const __half2* bbase = Bst + (kt & 1) * B_TILE;
        const __half2* arow  = &As[(wm * 16 + g) * AS_STRIDE + jb];
        const __half2* arow8 = &As[(wm * 16 + g + 8) * AS_STRIDE + jb];
        uint32_t a0 = *(const uint32_t*)&arow[t4];
        uint32_t a1 = *(const uint32_t*)&arow8[t4];
        uint32_t a2 = *(const uint32_t*)&arow[t4 + 4];
        uint32_t a3 = *(const uint32_t*)&arow8[t4 + 4];
#pragma unroll
        for (int nt = 0; nt < 12; nt++) {
            int col = wn * 96 + nt * 8 + g;
            uint32_t b0 = *(const uint32_t*)&bbase[col * B_STRIDE + t4];
            uint32_t b1 = *(const uint32_t*)&bbase[col * B_STRIDE + t4 + 4];
            asm volatile(
                "mma.sync.aligned.m16n8k16.row.col.f32.f16.f16.f32 "
                "{%0,%1,%2,%3}, {%4,%5,%6,%7}, {%8,%9}, {%0,%1,%2,%3};"
                : "+f"(acc[nt][0]), "+f"(acc[nt][1]),
                  "+f"(acc[nt][2]), "+f"(acc[nt][3])
                : "r"(a0), "r"(a1), "r"(a2), "r"(a3), "r"(b0), "r"(b1));
        }

        __syncthreads();        // all warps done reading buf kt&1
        if (kt < 10) load_btile(kt + 2, kt & 1);
    }

    int rA = row0 + wm * 16 + g;
#pragma unroll
    for (int nt = 0; nt < 12; nt++) {
        int col = wn * 96 + nt * 8 + t4 * 2;
        float2* p0 = (float2*)(out + (size_t)rA * IND + col);
        float2 v0 = *p0;
        v0.x += acc[nt][0]; v0.y += acc[nt][1];
        *p0 = v0;
        float2* p1 = (float2*)(out + (size_t)(rA + 8) * IND + col);
        float2 v1 = *p1;
        v1.x += acc[nt][2]; v1.y += acc[nt][3];
        *p1 = v1;
    }
}

// ======================= launch ==============================================
extern "C" void kernel_launch(void* const* d_in, const int* in_sizes, int n_in,
                              void* d_out, int out_size) {
    const float* query = (const float*)d_in[0];
    const float* f_xz  = (const float*)d_in[1];
    const float* f_xy  = (const float*)d_in[2];
    const float* f_yz  = (const float*)d_in[3];
    const float* W_v   = (const float*)d_in[4];
    const float* b_v   = (const float*)d_in[5];
    const float* W_out = (const float*)d_in[6];
    const float* b_out = (const float*)d_in[7];
    const float* W_off = (const float*)d_in[8];
    const float* b_off = (const float*)d_in[9];
    const float* W_wt  = (const float*)d_in[10];
    const float* b_wt  = (const float*)d_in[11];
    float* out = (float*)d_out;

    cudaFuncSetAttribute(auxgemm_k, cudaFuncAttributeMaxDynamicSharedMemorySize,
                         AUXG_SMEM);

    transpose_k<<<dim3(HW / 32, CPL / 32, 12), dim3(32, 8)>>>(f_xz, f_xy, f_yz);
    prep_k<<<IND, IND>>>(W_v, b_v, W_out);
    featA_k<<<2048, 256>>>(query, W_off, b_off, W_wt, b_wt, b_out, out);
    auxgemm_k<<<NPTS / 64, 256, AUXG_SMEM>>>(out);
}